// round 6
// baseline (speedup 1.0000x reference)
#include <cuda_runtime.h>

#define BB   8
#define TT   48
#define CC   684
#define HH   16
#define WWD  64
#define HWN  1024
#define HIDN 256
#define AA   512
#define VV   111
#define LOCN 432
#define NBLK 128

typedef unsigned long long u64;

// ---------------- device scratch (static; no allocation) ----------------
__device__ unsigned g_barcnt;
__device__ float g_mask2[BB*HWN];
__device__ float g_avg[BB*CC];
__device__ float g_query[BB*AA];
__device__ float g_alpha_sum[BB*HWN];
__device__ float g_energy[BB*HWN];
__device__ float g_ctx[BB*CC];
__device__ float g_ipart[64*HIDN];
__device__ float g_lpart[64*HIDN];
__device__ float g_M[121*AA];          // fused K_cov * W_cov
__device__ float g_KfT[CC*AA];         // K_feat transposed [c][a]
__device__ float g_WihT[HIDN*768];     // [i][gate_j]
__device__ float g_WhhT[HIDN*768];
__device__ float g_trans[(size_t)BB*HWN*AA]; // 16.7 MB, L2-resident

__device__ __forceinline__ float wred(float v){
    #pragma unroll
    for (int o=16;o;o>>=1) v += __shfl_xor_sync(0xFFFFFFFFu, v, o);
    return v;
}
__device__ __forceinline__ float ftanh(float x){
    return 1.f - __fdividef(2.f, __expf(2.f*x) + 1.f);
}
__device__ __forceinline__ float fsig(float x){
    return __fdividef(1.f, 1.f + __expf(-x));
}
// packed fp32x2 FMA (Blackwell): one instr = two IEEE fp32 FMAs
__device__ __forceinline__ u64 ffma2(u64 a, u64 b, u64 c){
    u64 d;
    asm("fma.rn.f32x2 %0, %1, %2, %3;" : "=l"(d) : "l"(a), "l"(b), "l"(c));
    return d;
}
__device__ __forceinline__ u64 pack2(float x, float y){
    u64 d; asm("mov.b64 %0, {%1, %2};" : "=l"(d) : "f"(x), "f"(y)); return d;
}
__device__ __forceinline__ void unpack2(u64 v, float& x, float& y){
    asm("mov.b64 {%0, %1}, %2;" : "=f"(x), "=f"(y) : "l"(v));
}

// grid-wide barrier (canonical ordering; validated in round 5)
__device__ __forceinline__ void gsync(unsigned &target){
    __threadfence();
    __syncthreads();
    target += NBLK;
    if (threadIdx.x == 0){
        atomicAdd(&g_barcnt, 1u);
        unsigned v;
        do {
            asm volatile("ld.acquire.gpu.u32 %0, [%1];" : "=r"(v) : "l"(&g_barcnt) : "memory");
        } while (v < target);
    }
    __syncthreads();
}

// ---------------- setup kernels ----------------

__global__ void k_prep_w(const float* __restrict__ W_ih,
                         const float* __restrict__ W_hh,
                         const float* __restrict__ K_feat){
    int i = blockIdx.x*256 + threadIdx.x;
    if (i < 768*256){
        int r = i/256, c = i%256;
        g_WihT[c*768 + r] = W_ih[i];
        g_WhhT[c*768 + r] = W_hh[i];
    }
    if (i < 512*684){
        int a = i/684, c = i%684;
        g_KfT[c*512 + a] = K_feat[i];
    }
}

// M[p][a] = sum_c K_cov[c][p] * W_cov[c][a]
__global__ void k_covM(const float* __restrict__ K_cov,
                       const float* __restrict__ W_cov){
    int p = blockIdx.x, a = threadIdx.x;
    float s0 = 0.f, s1 = 0.f;
    #pragma unroll 4
    for (int c=0;c<512;c++){
        float k = K_cov[c*121 + p];
        s0 += k * W_cov[c*512 + a];
        s1 += k * W_cov[c*512 + 256 + a];
    }
    g_M[p*AA + a]       = s0;
    g_M[p*AA + 256 + a] = s1;
}

// mask2 downsample + avg pooling + alpha_sum zero + barrier reset
__global__ void __launch_bounds__(256) k_avgmask(const float* __restrict__ imask,
                                                 const float* __restrict__ cnn){
    int slice = blockIdx.x, b = blockIdx.y;
    int tid = threadIdx.x, wid = tid>>5, lane = tid&31;
    __shared__ float msh[HWN];
    __shared__ float sred[8];
    float s = 0.f;
    #pragma unroll
    for (int k=0;k<4;k++){
        int hw = tid + 256*k;
        int h = hw >> 6, w = hw & 63;
        float v = imask[(size_t)b*262144 + (size_t)(h*16)*1024 + w*16];
        msh[hw] = v; s += v;
        if (slice == 0){
            g_mask2[b*HWN + hw] = v;
            g_alpha_sum[b*HWN + hw] = 0.f;
        }
    }
    if (slice == 0 && b == 0 && tid == 0) g_barcnt = 0u;
    s = wred(s);
    if (lane == 0) sred[wid] = s;
    __syncthreads();
    float tot = 0.f;
    #pragma unroll
    for (int i=0;i<8;i++) tot += sred[i];
    float inv = __fdividef(1.f, tot);
    int c0 = slice*86, cend = min(CC, c0+86);
    for (int c=c0+wid;c<cend;c+=8){
        const float* p = cnn + (size_t)(b*CC + c)*HWN;
        float acc = 0.f;
        #pragma unroll
        for (int m=0;m<32;m++) acc += msh[lane + 32*m] * p[lane + 32*m];
        acc = wred(acc);
        if (lane == 0) g_avg[b*CC + c] = acc*inv;
    }
}

// one-time 1x1 conv, FFMA2 version
__global__ void __launch_bounds__(256) k_trans(const float* __restrict__ cnn,
                                               const float* __restrict__ b_feat){
    int w0 = blockIdx.x*32, h = blockIdx.y, b = blockIdx.z;
    int tid = threadIdx.x;
    __shared__ __align__(16) float X[64][32];
    u64 acc0[16], acc1[16];
    #pragma unroll
    for (int i=0;i<16;i++){ acc0[i]=0ull; acc1[i]=0ull; }
    for (int c0=0;c0<CC;c0+=64){
        int nc = min(64, CC-c0);
        __syncthreads();
        for (int idx=tid; idx<nc*32; idx+=256){
            int cc = idx>>5, pix = idx&31;
            X[cc][pix] = cnn[(size_t)(b*CC + c0+cc)*HWN + h*WWD + w0 + pix];
        }
        __syncthreads();
        for (int cc=0; cc<nc; cc++){
            float k0 = g_KfT[(c0+cc)*AA + tid];
            float k1 = g_KfT[(c0+cc)*AA + 256 + tid];
            u64 k0p = pack2(k0,k0), k1p = pack2(k1,k1);
            #pragma unroll
            for (int k=0;k<16;k++){
                u64 x = *(const u64*)&X[cc][2*k];
                acc0[k] = ffma2(x, k0p, acc0[k]);
                acc1[k] = ffma2(x, k1p, acc1[k]);
            }
        }
    }
    float bf0 = b_feat[tid], bf1 = b_feat[256+tid];
    #pragma unroll
    for (int k=0;k<16;k++){
        float a0x,a0y,a1x,a1y;
        unpack2(acc0[k], a0x, a0y);
        unpack2(acc1[k], a1x, a1y);
        size_t gp0 = (size_t)((b*HH + h)*WWD + w0 + 2*k)*AA;
        size_t gp1 = gp0 + AA;
        g_trans[gp0 + tid]       = a0x + bf0;
        g_trans[gp0 + 256 + tid] = a1x + bf1;
        g_trans[gp1 + tid]       = a0y + bf0;
        g_trans[gp1 + 256 + tid] = a1y + bf1;
    }
}

// ---------------- persistent kernel shared overlays ----------------
struct SB { float nb[11][44]; float nbo[11][44]; float part[32][256]; };
struct SC { float am[HWN]; };
struct SD { float ein[256]; float gi[768]; float gh[768]; float ctx[CC];
            float op[4][256]; float out[256]; float vals[128]; };

// ---------------- persistent scan kernel ----------------
__global__ void __launch_bounds__(256) k_persist(
    const int*   __restrict__ labels,  const float* __restrict__ emb,
    const float* __restrict__ b_ih,    const float* __restrict__ b_hh,
    const float* __restrict__ W_q,     const float* __restrict__ b_q,
    const float* __restrict__ w_alpha, const float* __restrict__ b_alpha,
    const float* __restrict__ cnn,
    const float* __restrict__ W_state, const float* __restrict__ b_state,
    const float* __restrict__ W_emb,   const float* __restrict__ b_emb,
    const float* __restrict__ W_ctx,   const float* __restrict__ b_ctx,
    const float* __restrict__ W_out,   const float* __restrict__ b_out,
    const float* __restrict__ W_init,  const float* __restrict__ b_init,
    const float* __restrict__ locp,    const float* __restrict__ W_loc,
    const float* __restrict__ b_loc,
    float* __restrict__ probs_out, float* __restrict__ alphas_out,
    float* __restrict__ ctxs_out,  float* __restrict__ outs_out){

    int blk = blockIdx.x;
    int tid = threadIdx.x, wid = tid>>5, lane = tid&31;
    unsigned bar = 0;

    __shared__ __align__(16) char s_raw[sizeof(SB)];
    SB* sB = (SB*)s_raw;
    SC* sC = (SC*)s_raw;
    SD* sD = (SD*)s_raw;
    __shared__ float s_hid[HIDN];    // persistent (blk<8)
    __shared__ float s_et[HIDN];     // persistent (blk<8)
    __shared__ float s_locw[HIDN];   // persistent (blk<8)
    __shared__ float s_red[8];
    __shared__ float s_bc[2];

    // ======== pre-phase P1: init partials (all 128 blocks) ========
    {
        if (blk < 64){
            int b = blk>>3, sl = blk&7;
            int c0 = sl*86, n = min(CC, c0+86) - c0;
            for (int i=tid;i<n;i+=256) sD->vals[i] = g_avg[b*CC + c0 + i];
            __syncthreads();
            float p = 0.f;
            for (int rr=0; rr<n; rr++) p += sD->vals[rr]*W_init[(c0+rr)*HIDN + tid];
            g_ipart[(b*8 + sl)*HIDN + tid] = p;
        } else {
            int b = (blk-64)>>3, sl = (blk-64)&7;
            int l0 = sl*54;
            for (int i=tid;i<54;i+=256) sD->vals[i] = locp[b*LOCN + l0 + i];
            __syncthreads();
            float p = 0.f;
            #pragma unroll 2
            for (int rr=0; rr<54; rr++) p += sD->vals[rr]*W_loc[(l0+rr)*HIDN + tid];
            g_lpart[(b*8 + sl)*HIDN + tid] = p;
        }
    }
    gsync(bar);

    // ======== pre-phase P2: combine init + A(0) (blk<8) ========
    if (blk < 8){
        int b = blk, j = tid;
        float h0 = b_init[j];
        float lw = b_loc[j];
        #pragma unroll
        for (int p=0;p<8;p++){
            h0 += g_ipart[(b*8 + p)*HIDN + j];
            lw += g_lpart[(b*8 + p)*HIDN + j];
        }
        s_hid[j] = ftanh(h0);
        s_locw[j] = lw;
        __syncthreads();
        // ---- A(0): GRU + query ----
        {
            int tok = 1;
            sD->ein[tid] = emb[tok*HIDN + tid];
            __syncthreads();
            if (tid < 192){
                float4 gi = {0,0,0,0}, gh = {0,0,0,0};
                #pragma unroll 4
                for (int i=0;i<HIDN;i++){
                    float e = sD->ein[i], hh = s_hid[i];
                    float4 wi = *(const float4*)&g_WihT[i*768 + 4*tid];
                    float4 wh = *(const float4*)&g_WhhT[i*768 + 4*tid];
                    gi.x += e*wi.x; gi.y += e*wi.y; gi.z += e*wi.z; gi.w += e*wi.w;
                    gh.x += hh*wh.x; gh.y += hh*wh.y; gh.z += hh*wh.z; gh.w += hh*wh.w;
                }
                ((float4*)sD->gi)[tid] = gi;
                ((float4*)sD->gh)[tid] = gh;
            }
            __syncthreads();
            {
                float r = fsig(sD->gi[j] + b_ih[j] + sD->gh[j] + b_hh[j]);
                float z = fsig(sD->gi[256+j] + b_ih[256+j] + sD->gh[256+j] + b_hh[256+j]);
                float n = ftanh(sD->gi[512+j] + b_ih[512+j] + r*(sD->gh[512+j] + b_hh[512+j]));
                float hn = (1.f - z)*n + z*s_hid[j];
                __syncthreads();
                s_hid[j] = hn;
                s_et[j] = sD->ein[j];
            }
            __syncthreads();
            if (tid < 128){
                float4 q = *(const float4*)&b_q[4*tid];
                #pragma unroll 4
                for (int i=0;i<HIDN;i++){
                    float hv = s_hid[i];
                    float4 wq = *(const float4*)&W_q[i*AA + 4*tid];
                    q.x += hv*wq.x; q.y += hv*wq.y; q.z += hv*wq.z; q.w += hv*wq.w;
                }
                __stcg((float4*)&g_query[b*AA + 4*tid], q);
            }
        }
    }
    gsync(bar);

    // ======== scan ========
    for (int t = 0; t < TT; t++){
        // ---- B: coverage-conv + energy (all 128 blocks; (b, h); 2 tiles) ----
        {
            int b = blk >> 4, h = blk & 15;
            float q0 = __ldcg(&g_query[b*AA + tid]);
            float q1 = __ldcg(&g_query[b*AA + 256 + tid]);
            float wa0 = w_alpha[tid], wa1 = w_alpha[256 + tid];
            float ba = b_alpha[0];
            for (int tile=0; tile<2; tile++){
                int w0 = tile*32;
                __syncthreads();
                for (int idx=tid; idx<11*42; idx+=256){
                    int r = idx/42, cc = idx%42;
                    int gh = h - 5 + r, gw = w0 - 5 + cc;
                    float v = 0.f;
                    if (gh >= 0 && gh < HH && gw >= 0 && gw < WWD)
                        v = __ldcg(&g_alpha_sum[b*HWN + gh*WWD + gw]);
                    sB->nb[r][cc] = v;
                    if (cc > 0) sB->nbo[r][cc-1] = v;
                }
                __syncthreads();
                u64 acc0[16], acc1[16];
                #pragma unroll
                for (int i=0;i<16;i++){ acc0[i]=0ull; acc1[i]=0ull; }
                #pragma unroll 1
                for (int py=0; py<11; py++){
                    float m0v[11], m1v[11];
                    #pragma unroll
                    for (int px=0;px<11;px++){
                        int p = py*11 + px;
                        m0v[px] = g_M[p*AA + tid];
                        m1v[px] = g_M[p*AA + 256 + tid];
                    }
                    u64 pe[21], po[20];
                    #pragma unroll
                    for (int i=0;i<21;i++) pe[i] = *(const u64*)&sB->nb[py][2*i];
                    #pragma unroll
                    for (int i=0;i<20;i++) po[i] = *(const u64*)&sB->nbo[py][2*i];
                    #pragma unroll
                    for (int px=0; px<11; px++){
                        u64 m0 = pack2(m0v[px], m0v[px]);
                        u64 m1 = pack2(m1v[px], m1v[px]);
                        #pragma unroll
                        for (int k=0;k<16;k++){
                            u64 v = (px & 1) ? po[((px-1)>>1)+k] : pe[(px>>1)+k];
                            acc0[k] = ffma2(v, m0, acc0[k]);
                            acc1[k] = ffma2(v, m1, acc1[k]);
                        }
                    }
                }
                size_t gbase = (size_t)((b*HH + h)*WWD + w0)*AA + tid;
                #pragma unroll
                for (int k=0;k<16;k++){
                    float a0x,a0y,a1x,a1y;
                    unpack2(acc0[k], a0x, a0y);
                    unpack2(acc1[k], a1x, a1y);
                    float s0a = ftanh(q0 + g_trans[gbase + (size_t)(2*k)*AA]       + a0x);
                    float s1a = ftanh(q1 + g_trans[gbase + (size_t)(2*k)*AA + 256] + a1x);
                    float s0b = ftanh(q0 + g_trans[gbase + (size_t)(2*k+1)*AA]       + a0y);
                    float s1b = ftanh(q1 + g_trans[gbase + (size_t)(2*k+1)*AA + 256] + a1y);
                    sB->part[2*k][tid]   = wa0*s0a + wa1*s1a;
                    sB->part[2*k+1][tid] = wa0*s0b + wa1*s1b;
                }
                __syncthreads();
                #pragma unroll
                for (int k=0;k<4;k++){
                    int pix = wid*4 + k;
                    float s = 0.f;
                    #pragma unroll
                    for (int m=0;m<8;m++) s += sB->part[pix][lane + 32*m];
                    s = wred(s);
                    if (lane == 0) __stcg(&g_energy[b*HWN + h*WWD + w0 + pix], s + ba);
                }
            }
        }
        gsync(bar);

        // ---- C: softmax (redundant) + ctx (all 128; (b, chunk16)) ----
        {
            int b = blk >> 4, chunk = blk & 15;
            float mx = -1e30f;
            #pragma unroll
            for (int m=0;m<8;m++){
                float4 e4v = __ldcg((const float4*)&g_energy[tid*4 + 1024*m]);
                mx = fmaxf(mx, fmaxf(fmaxf(e4v.x, e4v.y), fmaxf(e4v.z, e4v.w)));
            }
            #pragma unroll
            for (int o=16;o;o>>=1) mx = fmaxf(mx, __shfl_xor_sync(0xFFFFFFFFu, mx, o));
            if (lane == 0) s_red[wid] = mx;
            __syncthreads();
            if (tid == 0){
                float m2 = s_red[0];
                #pragma unroll
                for (int i=1;i<8;i++) m2 = fmaxf(m2, s_red[i]);
                s_bc[0] = m2;
            }
            __syncthreads();
            mx = s_bc[0];
            float e4[4]; float loc = 0.f;
            int base = b*HWN + tid*4;
            float4 ein = __ldcg((const float4*)&g_energy[base]);
            float4 msk = *(const float4*)&g_mask2[base];
            e4[0] = __expf(ein.x - mx)*msk.x;
            e4[1] = __expf(ein.y - mx)*msk.y;
            e4[2] = __expf(ein.z - mx)*msk.z;
            e4[3] = __expf(ein.w - mx)*msk.w;
            loc = e4[0]+e4[1]+e4[2]+e4[3];
            loc = wred(loc);
            __syncthreads();
            if (lane == 0) s_red[wid] = loc;
            __syncthreads();
            if (tid == 0){
                float s = 0.f;
                #pragma unroll
                for (int i=0;i<8;i++) s += s_red[i];
                s_bc[1] = __fdividef(1.f, s + 1e-10f);
            }
            __syncthreads();
            float inv = s_bc[1];
            #pragma unroll
            for (int k=0;k<4;k++){
                float a = e4[k]*inv;
                int hw = tid*4 + k;
                sC->am[hw] = (a > 0.02f) ? a : 0.f;
                if (chunk == 0){
                    alphas_out[(size_t)(b*TT + t)*HWN + hw] = a;
                    float as = __ldcg(&g_alpha_sum[b*HWN + hw]) + a;
                    __stcg(&g_alpha_sum[b*HWN + hw], as);
                }
            }
            __syncthreads();
            int c0 = chunk*43, cend = min(CC, c0+43);
            for (int c = c0 + wid; c < cend; c += 8){
                const float* p = cnn + (size_t)(b*CC + c)*HWN;
                float s = 0.f;
                #pragma unroll
                for (int m=0;m<8;m++){
                    float4 a4 = *(const float4*)&sC->am[lane*4 + 128*m];
                    float4 p4 = *(const float4*)&p[lane*4 + 128*m];
                    s += a4.x*p4.x + a4.y*p4.y + a4.z*p4.z + a4.w*p4.w;
                }
                s = wred(s);
                if (lane == 0){
                    __stcg(&g_ctx[b*CC + c], s);
                    ctxs_out[(size_t)t*BB*CC + b*CC + c] = s;
                }
            }
        }
        gsync(bar);

        // ---- D(t) + A(t+1) (blk<8) ----
        if (blk < 8){
            int b = blk, j = tid;
            // stage ctx
            for (int i=tid;i<CC;i+=256) sD->ctx[i] = __ldcg(&g_ctx[b*CC + i]);
            __syncthreads();
            // out_state partials: rg in 0..3, 299 rows each; cols 4*ct
            {
                int rg = tid>>6, ct = tid&63;
                float4 acc = {0,0,0,0};
                int lo = rg*299, hi = lo + 299;
                int r = lo;
                int e1 = min(hi, 256);
                for (; r < e1; r++){
                    float v = s_hid[r];
                    float4 w = *(const float4*)&W_state[r*HIDN + 4*ct];
                    acc.x += v*w.x; acc.y += v*w.y; acc.z += v*w.z; acc.w += v*w.w;
                }
                r = max(lo, 256);
                int e2 = min(hi, 512);
                for (; r < e2; r++){
                    float v = s_et[r-256];
                    float4 w = *(const float4*)&W_emb[(r-256)*HIDN + 4*ct];
                    acc.x += v*w.x; acc.y += v*w.y; acc.z += v*w.z; acc.w += v*w.w;
                }
                r = max(lo, 512);
                for (; r < hi; r++){
                    float v = sD->ctx[r-512];
                    float4 w = *(const float4*)&W_ctx[(r-512)*HIDN + 4*ct];
                    acc.x += v*w.x; acc.y += v*w.y; acc.z += v*w.z; acc.w += v*w.w;
                }
                ((float4*)&sD->op[rg][0])[ct] = acc;
            }
            __syncthreads();
            {
                float s = b_state[j] + b_emb[j] + b_ctx[j]
                        + sD->op[0][j] + sD->op[1][j] + sD->op[2][j] + sD->op[3][j];
                s = fmaxf(s, s_locw[j]);
                outs_out[(size_t)t*BB*HIDN + b*HIDN + j] = s;
                sD->out[j] = s;
            }
            __syncthreads();
            if (j < VV){
                float pr = b_out[j];
                #pragma unroll 8
                for (int i=0;i<HIDN;i++) pr += sD->out[i]*W_out[i*VV + j];
                probs_out[(size_t)(b*TT + t)*VV + j] = pr;
            }
            // ---- A(t+1) ----
            if (t + 1 < TT){
                int tok = labels[b*TT + t];
                __syncthreads();
                sD->ein[tid] = emb[tok*HIDN + tid];
                __syncthreads();
                if (tid < 192){
                    float4 gi = {0,0,0,0}, gh = {0,0,0,0};
                    #pragma unroll 4
                    for (int i=0;i<HIDN;i++){
                        float e = sD->ein[i], hh = s_hid[i];
                        float4 wi = *(const float4*)&g_WihT[i*768 + 4*tid];
                        float4 wh = *(const float4*)&g_WhhT[i*768 + 4*tid];
                        gi.x += e*wi.x; gi.y += e*wi.y; gi.z += e*wi.z; gi.w += e*wi.w;
                        gh.x += hh*wh.x; gh.y += hh*wh.y; gh.z += hh*wh.z; gh.w += hh*wh.w;
                    }
                    ((float4*)sD->gi)[tid] = gi;
                    ((float4*)sD->gh)[tid] = gh;
                }
                __syncthreads();
                {
                    float r = fsig(sD->gi[j] + b_ih[j] + sD->gh[j] + b_hh[j]);
                    float z = fsig(sD->gi[256+j] + b_ih[256+j] + sD->gh[256+j] + b_hh[256+j]);
                    float n = ftanh(sD->gi[512+j] + b_ih[512+j] + r*(sD->gh[512+j] + b_hh[512+j]));
                    float hn = (1.f - z)*n + z*s_hid[j];
                    __syncthreads();
                    s_hid[j] = hn;
                    s_et[j] = sD->ein[j];
                }
                __syncthreads();
                if (tid < 128){
                    float4 q = *(const float4*)&b_q[4*tid];
                    #pragma unroll 4
                    for (int i=0;i<HIDN;i++){
                        float hv = s_hid[i];
                        float4 wq = *(const float4*)&W_q[i*AA + 4*tid];
                        q.x += hv*wq.x; q.y += hv*wq.y; q.z += hv*wq.z; q.w += hv*wq.w;
                    }
                    __stcg((float4*)&g_query[b*AA + 4*tid], q);
                }
            }
        }
        gsync(bar);
    }
}

// ---------------- launch ----------------
extern "C" void kernel_launch(void* const* d_in, const int* in_sizes, int n_in,
                              void* d_out, int out_size){
    const float* cnn     = (const float*)d_in[0];
    const int*   labels  = (const int*  )d_in[1];
    const float* locp    = (const float*)d_in[2];
    const float* imask   = (const float*)d_in[3];
    const float* W_init  = (const float*)d_in[5];
    const float* b_init  = (const float*)d_in[6];
    const float* emb     = (const float*)d_in[7];
    const float* W_ih    = (const float*)d_in[8];
    const float* W_hh    = (const float*)d_in[9];
    const float* b_ih    = (const float*)d_in[10];
    const float* b_hh    = (const float*)d_in[11];
    const float* W_q     = (const float*)d_in[12];
    const float* b_q     = (const float*)d_in[13];
    const float* K_cov   = (const float*)d_in[14];
    const float* W_cov   = (const float*)d_in[15];
    const float* w_alpha = (const float*)d_in[16];
    const float* b_alpha = (const float*)d_in[17];
    const float* K_feat  = (const float*)d_in[18];
    const float* b_feat  = (const float*)d_in[19];
    const float* W_state = (const float*)d_in[20];
    const float* b_state = (const float*)d_in[21];
    const float* W_emb   = (const float*)d_in[22];
    const float* b_emb   = (const float*)d_in[23];
    const float* W_ctx   = (const float*)d_in[24];
    const float* b_ctx   = (const float*)d_in[25];
    const float* W_out   = (const float*)d_in[26];
    const float* b_out   = (const float*)d_in[27];
    const float* W_loc   = (const float*)d_in[28];
    const float* b_loc   = (const float*)d_in[29];

    float* out        = (float*)d_out;
    float* probs_out  = out;                                   // B*T*V
    float* alphas_out = probs_out + (size_t)BB*TT*VV;          // B*T*H*W
    float* ctxs_out   = alphas_out + (size_t)BB*TT*HWN;        // T*B*C
    float* outs_out   = ctxs_out + (size_t)TT*BB*CC;           // T*B*HID

    k_prep_w<<<(512*684 + 255)/256, 256>>>(W_ih, W_hh, K_feat);
    k_covM<<<121, 256>>>(K_cov, W_cov);
    k_avgmask<<<dim3(8, BB), 256>>>(imask, cnn);
    k_trans<<<dim3(2, HH, BB), 256>>>(cnn, b_feat);

    k_persist<<<NBLK, 256>>>(labels, emb, b_ih, b_hh, W_q, b_q,
                             w_alpha, b_alpha, cnn,
                             W_state, b_state, W_emb, b_emb,
                             W_ctx, b_ctx, W_out, b_out,
                             W_init, b_init, locp, W_loc, b_loc,
                             probs_out, alphas_out, ctxs_out, outs_out);
    (void)in_sizes; (void)n_in; (void)out_size;
}

// round 7
// speedup vs baseline: 1.1266x; 1.1266x over previous
#include <cuda_runtime.h>

#define BB   8
#define TT   48
#define CC   684
#define HH   16
#define WWD  64
#define HWN  1024
#define HIDN 256
#define AA   512
#define VV   111
#define LOCN 432
#define NBLK 128

typedef unsigned long long u64;

// ---------------- device scratch (static; no allocation) ----------------
__device__ unsigned g_barcnt;
__device__ float g_mask2[BB*HWN];
__device__ float g_avg[BB*CC];
__device__ float g_hidden[BB*HIDN];
__device__ float g_locw[BB*HIDN];
__device__ float g_query[BB*AA];
__device__ float g_et[BB*HIDN];
__device__ float g_alpha_sum[BB*HWN];
__device__ float g_energy[BB*HWN];
__device__ float g_ctx[BB*CC];
__device__ float g_gpart[BB*16*6*HIDN];
__device__ float g_opart[BB*4*HIDN];
__device__ float2 g_Mp[121*256];       // paired (M[p][a], M[p][a+256])
__device__ float g_KfT[CC*AA];         // K_feat transposed [c][a]
__device__ float g_WihT[HIDN*768];     // [i][gate_j]
__device__ float g_WhhT[HIDN*768];
__device__ float g_trans[(size_t)BB*HWN*AA]; // 16.7 MB, L2-resident

__device__ __forceinline__ float wred(float v){
    #pragma unroll
    for (int o=16;o;o>>=1) v += __shfl_xor_sync(0xFFFFFFFFu, v, o);
    return v;
}
__device__ __forceinline__ float ftanh(float x){
    return 1.f - __fdividef(2.f, __expf(2.f*x) + 1.f);
}
__device__ __forceinline__ float fsig(float x){
    return __fdividef(1.f, 1.f + __expf(-x));
}
// packed fp32x2 FMA (Blackwell): one instr = two IEEE fp32 FMAs
__device__ __forceinline__ u64 ffma2(u64 a, u64 b, u64 c){
    u64 d;
    asm("fma.rn.f32x2 %0, %1, %2, %3;" : "=l"(d) : "l"(a), "l"(b), "l"(c));
    return d;
}
__device__ __forceinline__ u64 pack2(float x, float y){
    u64 d; asm("mov.b64 %0, {%1, %2};" : "=l"(d) : "f"(x), "f"(y)); return d;
}
__device__ __forceinline__ void unpack2(u64 v, float& x, float& y){
    asm("mov.b64 {%0, %1}, %2;" : "=f"(x), "=f"(y) : "l"(v));
}

// grid-wide barrier (canonical ordering; validated in round 5)
__device__ __forceinline__ void gsync(unsigned &target){
    __threadfence();
    __syncthreads();
    target += NBLK;
    if (threadIdx.x == 0){
        atomicAdd(&g_barcnt, 1u);
        unsigned v;
        do {
            asm volatile("ld.acquire.gpu.u32 %0, [%1];" : "=r"(v) : "l"(&g_barcnt) : "memory");
        } while (v < target);
    }
    __syncthreads();
}

// ---------------- setup kernels ----------------

__global__ void k_prep_w(const float* __restrict__ W_ih,
                         const float* __restrict__ W_hh,
                         const float* __restrict__ K_feat){
    int i = blockIdx.x*256 + threadIdx.x;
    if (i < 768*256){
        int r = i/256, c = i%256;
        g_WihT[c*768 + r] = W_ih[i];
        g_WhhT[c*768 + r] = W_hh[i];
    }
    if (i < 512*684){
        int a = i/684, c = i%684;
        g_KfT[c*512 + a] = K_feat[i];
    }
}

// Mp[p][a] = (sum_c K_cov[c][p]*W_cov[c][a], sum_c K_cov[c][p]*W_cov[c][a+256])
__global__ void k_covM(const float* __restrict__ K_cov,
                       const float* __restrict__ W_cov){
    int p = blockIdx.x, a = threadIdx.x;
    float s0 = 0.f, s1 = 0.f;
    #pragma unroll 4
    for (int c=0;c<512;c++){
        float k = K_cov[c*121 + p];
        s0 += k * W_cov[c*512 + a];
        s1 += k * W_cov[c*512 + 256 + a];
    }
    g_Mp[p*256 + a] = make_float2(s0, s1);
}

// mask2 downsample + avg pooling + alpha_sum zero + barrier reset
__global__ void __launch_bounds__(256) k_avgmask(const float* __restrict__ imask,
                                                 const float* __restrict__ cnn){
    int slice = blockIdx.x, b = blockIdx.y;
    int tid = threadIdx.x, wid = tid>>5, lane = tid&31;
    __shared__ float msh[HWN];
    __shared__ float sred[8];
    float s = 0.f;
    #pragma unroll
    for (int k=0;k<4;k++){
        int hw = tid + 256*k;
        int h = hw >> 6, w = hw & 63;
        float v = imask[(size_t)b*262144 + (size_t)(h*16)*1024 + w*16];
        msh[hw] = v; s += v;
        if (slice == 0){
            g_mask2[b*HWN + hw] = v;
            g_alpha_sum[b*HWN + hw] = 0.f;
        }
    }
    if (slice == 0 && b == 0 && tid == 0) g_barcnt = 0u;
    s = wred(s);
    if (lane == 0) sred[wid] = s;
    __syncthreads();
    float tot = 0.f;
    #pragma unroll
    for (int i=0;i<8;i++) tot += sred[i];
    float inv = __fdividef(1.f, tot);
    int c0 = slice*86, cend = min(CC, c0+86);
    for (int c=c0+wid;c<cend;c+=8){
        const float* p = cnn + (size_t)(b*CC + c)*HWN;
        float acc = 0.f;
        #pragma unroll
        for (int m=0;m<32;m++) acc += msh[lane + 32*m] * p[lane + 32*m];
        acc = wred(acc);
        if (lane == 0) g_avg[b*CC + c] = acc*inv;
    }
}

// hidden0 = tanh(avg @ W_init), loc_w = locp @ W_loc
__global__ void __launch_bounds__(256) k_init2(
    const float* __restrict__ W_init, const float* __restrict__ b_init,
    const float* __restrict__ locp,   const float* __restrict__ W_loc,
    const float* __restrict__ b_loc){
    int b = blockIdx.x, j = threadIdx.x;
    __shared__ float avg[CC];
    __shared__ float lp[LOCN];
    for (int i=j;i<CC;i+=256) avg[i] = g_avg[b*CC + i];
    for (int i=j;i<LOCN;i+=256) lp[i] = locp[b*LOCN + i];
    __syncthreads();
    float h0 = b_init[j];
    #pragma unroll 4
    for (int c=0;c<CC;c++) h0 += avg[c]*W_init[c*HIDN + j];
    g_hidden[b*HIDN + j] = ftanh(h0);
    float lw = b_loc[j];
    #pragma unroll 4
    for (int l=0;l<LOCN;l++) lw += lp[l]*W_loc[l*HIDN + j];
    g_locw[b*HIDN + j] = lw;
}

// one-time 1x1 conv, FFMA2 version (profiled healthy in round 6)
__global__ void __launch_bounds__(256) k_trans(const float* __restrict__ cnn,
                                               const float* __restrict__ b_feat){
    int w0 = blockIdx.x*32, h = blockIdx.y, b = blockIdx.z;
    int tid = threadIdx.x;
    __shared__ __align__(16) float X[64][32];
    u64 acc0[16], acc1[16];
    #pragma unroll
    for (int i=0;i<16;i++){ acc0[i]=0ull; acc1[i]=0ull; }
    for (int c0=0;c0<CC;c0+=64){
        int nc = min(64, CC-c0);
        __syncthreads();
        for (int idx=tid; idx<nc*32; idx+=256){
            int cc = idx>>5, pix = idx&31;
            X[cc][pix] = cnn[(size_t)(b*CC + c0+cc)*HWN + h*WWD + w0 + pix];
        }
        __syncthreads();
        for (int cc=0; cc<nc; cc++){
            float k0 = g_KfT[(c0+cc)*AA + tid];
            float k1 = g_KfT[(c0+cc)*AA + 256 + tid];
            u64 k0p = pack2(k0,k0), k1p = pack2(k1,k1);
            #pragma unroll
            for (int k=0;k<16;k++){
                u64 x = *(const u64*)&X[cc][2*k];
                acc0[k] = ffma2(x, k0p, acc0[k]);
                acc1[k] = ffma2(x, k1p, acc1[k]);
            }
        }
    }
    float bf0 = b_feat[tid], bf1 = b_feat[256+tid];
    #pragma unroll
    for (int k=0;k<16;k++){
        float a0x,a0y,a1x,a1y;
        unpack2(acc0[k], a0x, a0y);
        unpack2(acc1[k], a1x, a1y);
        size_t gp0 = (size_t)((b*HH + h)*WWD + w0 + 2*k)*AA;
        size_t gp1 = gp0 + AA;
        g_trans[gp0 + tid]       = a0x + bf0;
        g_trans[gp0 + 256 + tid] = a1x + bf1;
        g_trans[gp1 + tid]       = a0y + bf0;
        g_trans[gp1 + 256 + tid] = a1y + bf1;
    }
}

// ---------------- persistent scan kernel (round-5 structure) ----------------
__global__ void __launch_bounds__(256) k_persist(
    const int*   __restrict__ labels,  const float* __restrict__ emb,
    const float* __restrict__ b_ih,    const float* __restrict__ b_hh,
    const float* __restrict__ W_q,     const float* __restrict__ b_q,
    const float* __restrict__ w_alpha, const float* __restrict__ b_alpha,
    const float* __restrict__ cnn,
    const float* __restrict__ W_state, const float* __restrict__ b_state,
    const float* __restrict__ W_emb,   const float* __restrict__ b_emb,
    const float* __restrict__ W_ctx,   const float* __restrict__ b_ctx,
    const float* __restrict__ W_out,   const float* __restrict__ b_out,
    float* __restrict__ probs_out, float* __restrict__ alphas_out,
    float* __restrict__ ctxs_out,  float* __restrict__ outs_out){

    int blk = blockIdx.x;
    int tid = threadIdx.x, wid = tid>>5, lane = tid&31;
    unsigned bar = 0;

    __shared__ __align__(16) float s_part[32][256];  // energy partials
    __shared__ __align__(8)  u64   s_nbd[11][42];    // duplicated-pair neighborhood
    __shared__ float s_am[HWN];
    __shared__ float s_vals[304];
    __shared__ float s_red[8];
    __shared__ float s_bc[2];

    for (int t = 0; t < TT; t++){
        // ---- A1: GRU gate partials (all 128 blocks; (b, part16)) ----
        {
            int b = blk >> 4, part = blk & 15;
            int tok = (t == 0) ? 1 : labels[b*TT + t - 1];
            if (tid < 16)       s_vals[tid] = emb[tok*HIDN + part*16 + tid];
            else if (tid < 32)  s_vals[tid] = __ldcg(&g_hidden[b*HIDN + part*16 + tid - 16]);
            __syncthreads();
            int j = tid;
            float p0=0.f,p1=0.f,p2=0.f,p3=0.f,p4=0.f,p5=0.f;
            #pragma unroll
            for (int ii=0; ii<16; ii++){
                int i = part*16 + ii;
                float e = s_vals[ii], hh = s_vals[16+ii];
                const float* wi = &g_WihT[i*768];
                const float* wh = &g_WhhT[i*768];
                p0 += e*wi[j];      p1 += e*wi[256+j];  p2 += e*wi[512+j];
                p3 += hh*wh[j];     p4 += hh*wh[256+j]; p5 += hh*wh[512+j];
            }
            float* gp = &g_gpart[(b*16 + part)*6*HIDN];
            __stcg(&gp[j], p0);      __stcg(&gp[256+j], p1);  __stcg(&gp[512+j], p2);
            __stcg(&gp[768+j], p3);  __stcg(&gp[1024+j], p4); __stcg(&gp[1280+j], p5);
        }
        gsync(bar);

        // ---- A2: combine gates -> hidden, e_t (8 blocks) ----
        if (blk < 8){
            int b = blk, j = tid;
            int tok = (t == 0) ? 1 : labels[b*TT + t - 1];
            float a0=b_ih[j], a1=b_ih[256+j], a2=b_ih[512+j];
            float a3=b_hh[j], a4=b_hh[256+j], a5=b_hh[512+j];
            #pragma unroll
            for (int p=0;p<16;p++){
                const float* gp = &g_gpart[(b*16 + p)*6*HIDN];
                a0 += __ldcg(&gp[j]);      a1 += __ldcg(&gp[256+j]);  a2 += __ldcg(&gp[512+j]);
                a3 += __ldcg(&gp[768+j]);  a4 += __ldcg(&gp[1024+j]); a5 += __ldcg(&gp[1280+j]);
            }
            float r = fsig(a0 + a3);
            float z = fsig(a1 + a4);
            float n = ftanh(a2 + r*a5);
            float hv = __ldcg(&g_hidden[b*HIDN + j]);
            float hn = (1.f - z)*n + z*hv;
            __stcg(&g_hidden[b*HIDN + j], hn);
            __stcg(&g_et[b*HIDN + j], emb[tok*HIDN + j]);
        }
        gsync(bar);

        // ---- A3: query = hn @ W_q (16 blocks; (b, half)) ----
        if (blk < 16){
            int b = blk >> 1, half = blk & 1;
            s_vals[tid] = __ldcg(&g_hidden[b*HIDN + tid]);
            __syncthreads();
            int j2 = half*256 + tid;
            float q = b_q[j2];
            #pragma unroll 8
            for (int i=0;i<HIDN;i++) q += s_vals[i]*W_q[i*AA + j2];
            __stcg(&g_query[b*AA + j2], q);
        }
        gsync(bar);

        // ---- B: coverage-conv + energy, FFMA2 alpha-pair packing ----
        {
            int b = blk >> 4, h = blk & 15;
            float q0 = __ldcg(&g_query[b*AA + tid]);
            float q1 = __ldcg(&g_query[b*AA + 256 + tid]);
            float wa0 = w_alpha[tid], wa1 = w_alpha[256 + tid];
            float ba = b_alpha[0];
            for (int tile=0; tile<2; tile++){
                int w0 = tile*32;
                __syncthreads();
                for (int idx=tid; idx<11*42; idx+=256){
                    int r = idx/42, cc = idx%42;
                    int gh = h - 5 + r, gw = w0 - 5 + cc;
                    float v = 0.f;
                    if (gh >= 0 && gh < HH && gw >= 0 && gw < WWD)
                        v = __ldcg(&g_alpha_sum[b*HWN + gh*WWD + gw]);
                    s_nbd[r][cc] = pack2(v, v);
                }
                __syncthreads();
                u64 acc[32];
                #pragma unroll
                for (int i=0;i<32;i++) acc[i]=0ull;
                #pragma unroll 1
                for (int py=0; py<11; py++){
                    u64 mp[11];
                    #pragma unroll
                    for (int px=0;px<11;px++){
                        float2 m2 = g_Mp[(py*11 + px)*256 + tid];
                        mp[px] = pack2(m2.x, m2.y);
                    }
                    #pragma unroll
                    for (int px=0; px<11; px++){
                        #pragma unroll
                        for (int pix=0;pix<32;pix++){
                            acc[pix] = ffma2(s_nbd[py][px+pix], mp[px], acc[pix]);
                        }
                    }
                }
                size_t gbase = (size_t)((b*HH + h)*WWD + w0)*AA + tid;
                #pragma unroll
                for (int pix=0;pix<32;pix++){
                    float a0, a1;
                    unpack2(acc[pix], a0, a1);
                    float s0 = ftanh(q0 + g_trans[gbase + (size_t)pix*AA]       + a0);
                    float s1 = ftanh(q1 + g_trans[gbase + (size_t)pix*AA + 256] + a1);
                    s_part[pix][tid] = wa0*s0 + wa1*s1;
                }
                __syncthreads();
                #pragma unroll
                for (int k=0;k<4;k++){
                    int pix = wid*4 + k;
                    float s = 0.f;
                    #pragma unroll
                    for (int m=0;m<8;m++) s += s_part[pix][lane + 32*m];
                    s = wred(s);
                    if (lane == 0) __stcg(&g_energy[b*HWN + h*WWD + w0 + pix], s + ba);
                }
            }
        }
        gsync(bar);

        // ---- C: softmax (redundant) + ctx (all 128; (b, chunk16)) ----
        {
            int b = blk >> 4, chunk = blk & 15;
            float mx = -1e30f;
            #pragma unroll
            for (int m=0;m<8;m++){
                float4 e4v = __ldcg((const float4*)&g_energy[tid*4 + 1024*m]);
                mx = fmaxf(mx, fmaxf(fmaxf(e4v.x, e4v.y), fmaxf(e4v.z, e4v.w)));
            }
            #pragma unroll
            for (int o=16;o;o>>=1) mx = fmaxf(mx, __shfl_xor_sync(0xFFFFFFFFu, mx, o));
            if (lane == 0) s_red[wid] = mx;
            __syncthreads();
            if (tid == 0){
                float m2 = s_red[0];
                #pragma unroll
                for (int i=1;i<8;i++) m2 = fmaxf(m2, s_red[i]);
                s_bc[0] = m2;
            }
            __syncthreads();
            mx = s_bc[0];
            float e4[4]; float loc = 0.f;
            int base = b*HWN + tid*4;
            float4 ein = __ldcg((const float4*)&g_energy[base]);
            float4 msk = *(const float4*)&g_mask2[base];
            e4[0] = __expf(ein.x - mx)*msk.x;
            e4[1] = __expf(ein.y - mx)*msk.y;
            e4[2] = __expf(ein.z - mx)*msk.z;
            e4[3] = __expf(ein.w - mx)*msk.w;
            loc = e4[0]+e4[1]+e4[2]+e4[3];
            loc = wred(loc);
            __syncthreads();
            if (lane == 0) s_red[wid] = loc;
            __syncthreads();
            if (tid == 0){
                float s = 0.f;
                #pragma unroll
                for (int i=0;i<8;i++) s += s_red[i];
                s_bc[1] = __fdividef(1.f, s + 1e-10f);
            }
            __syncthreads();
            float inv = s_bc[1];
            #pragma unroll
            for (int k=0;k<4;k++){
                float a = e4[k]*inv;
                int hw = tid*4 + k;
                s_am[hw] = (a > 0.02f) ? a : 0.f;
                if (chunk == 0){
                    alphas_out[(size_t)(b*TT + t)*HWN + hw] = a;
                    float as = __ldcg(&g_alpha_sum[b*HWN + hw]) + a;
                    __stcg(&g_alpha_sum[b*HWN + hw], as);
                }
            }
            __syncthreads();
            int c0 = chunk*43, cend = min(CC, c0+43);
            for (int c = c0 + wid; c < cend; c += 8){
                const float* p = cnn + (size_t)(b*CC + c)*HWN;
                float s = 0.f;
                #pragma unroll
                for (int m=0;m<8;m++){
                    float4 a4 = *(const float4*)&s_am[lane*4 + 128*m];
                    float4 p4 = *(const float4*)&p[lane*4 + 128*m];
                    s += a4.x*p4.x + a4.y*p4.y + a4.z*p4.z + a4.w*p4.w;
                }
                s = wred(s);
                if (lane == 0){
                    __stcg(&g_ctx[b*CC + c], s);
                    ctxs_out[(size_t)t*BB*CC + b*CC + c] = s;
                }
            }
        }
        gsync(bar);

        // ---- D1: out_state partials (32 blocks; (b, part4); 299 rows each) ----
        if (blk < 32){
            int b = blk >> 2, part = blk & 3;
            int lo = part*299, hi = lo + 299;
            for (int rr=tid; rr<299; rr+=256){
                int r = lo + rr;
                float v;
                if (r < 256)      v = __ldcg(&g_hidden[b*HIDN + r]);
                else if (r < 512) v = __ldcg(&g_et[b*HIDN + r - 256]);
                else              v = __ldcg(&g_ctx[b*CC + r - 512]);
                s_vals[rr] = v;
            }
            __syncthreads();
            int j = tid;
            float s = 0.f;
            int r = lo;
            int e1 = min(hi, 256);
            #pragma unroll 4
            for (; r < e1; r++) s += s_vals[r-lo]*W_state[r*HIDN + j];
            r = max(lo, 256);
            int e2 = min(hi, 512);
            #pragma unroll 4
            for (; r < e2; r++) s += s_vals[r-lo]*W_emb[(r-256)*HIDN + j];
            r = max(lo, 512);
            #pragma unroll 4
            for (; r < hi; r++) s += s_vals[r-lo]*W_ctx[(r-512)*HIDN + j];
            __stcg(&g_opart[(b*4 + part)*HIDN + j], s);
        }
        gsync(bar);

        // ---- D2: maxout + vocab projection (8 blocks) ----
        if (blk < 8){
            int b = blk, j = tid;
            float s = b_state[j] + b_emb[j] + b_ctx[j];
            #pragma unroll
            for (int p=0;p<4;p++) s += __ldcg(&g_opart[(b*4 + p)*HIDN + j]);
            s = fmaxf(s, g_locw[b*HIDN + j]);
            outs_out[(size_t)t*BB*HIDN + b*HIDN + j] = s;
            s_vals[j] = s;
            __syncthreads();
            if (j < VV){
                float pr = b_out[j];
                #pragma unroll 8
                for (int i=0;i<HIDN;i++) pr += s_vals[i]*W_out[i*VV + j];
                probs_out[(size_t)(b*TT + t)*VV + j] = pr;
            }
        }
        gsync(bar);
    }
}

// ---------------- launch ----------------
extern "C" void kernel_launch(void* const* d_in, const int* in_sizes, int n_in,
                              void* d_out, int out_size){
    const float* cnn     = (const float*)d_in[0];
    const int*   labels  = (const int*  )d_in[1];
    const float* locp    = (const float*)d_in[2];
    const float* imask   = (const float*)d_in[3];
    const float* W_init  = (const float*)d_in[5];
    const float* b_init  = (const float*)d_in[6];
    const float* emb     = (const float*)d_in[7];
    const float* W_ih    = (const float*)d_in[8];
    const float* W_hh    = (const float*)d_in[9];
    const float* b_ih    = (const float*)d_in[10];
    const float* b_hh    = (const float*)d_in[11];
    const float* W_q     = (const float*)d_in[12];
    const float* b_q     = (const float*)d_in[13];
    const float* K_cov   = (const float*)d_in[14];
    const float* W_cov   = (const float*)d_in[15];
    const float* w_alpha = (const float*)d_in[16];
    const float* b_alpha = (const float*)d_in[17];
    const float* K_feat  = (const float*)d_in[18];
    const float* b_feat  = (const float*)d_in[19];
    const float* W_state = (const float*)d_in[20];
    const float* b_state = (const float*)d_in[21];
    const float* W_emb   = (const float*)d_in[22];
    const float* b_emb   = (const float*)d_in[23];
    const float* W_ctx   = (const float*)d_in[24];
    const float* b_ctx   = (const float*)d_in[25];
    const float* W_out   = (const float*)d_in[26];
    const float* b_out   = (const float*)d_in[27];
    const float* W_loc   = (const float*)d_in[28];
    const float* b_loc   = (const float*)d_in[29];

    float* out        = (float*)d_out;
    float* probs_out  = out;                                   // B*T*V
    float* alphas_out = probs_out + (size_t)BB*TT*VV;          // B*T*H*W
    float* ctxs_out   = alphas_out + (size_t)BB*TT*HWN;        // T*B*C
    float* outs_out   = ctxs_out + (size_t)TT*BB*CC;           // T*B*HID

    k_prep_w<<<(512*684 + 255)/256, 256>>>(W_ih, W_hh, K_feat);
    k_covM<<<121, 256>>>(K_cov, W_cov);
    k_avgmask<<<dim3(8, BB), 256>>>(imask, cnn);
    k_init2<<<BB, 256>>>(W_init, b_init, locp, W_loc, b_loc);
    k_trans<<<dim3(2, HH, BB), 256>>>(cnn, b_feat);

    k_persist<<<NBLK, 256>>>(labels, emb, b_ih, b_hh, W_q, b_q,
                             w_alpha, b_alpha, cnn,
                             W_state, b_state, W_emb, b_emb,
                             W_ctx, b_ctx, W_out, b_out,
                             probs_out, alphas_out, ctxs_out, outs_out);
    (void)in_sizes; (void)n_in; (void)out_size;
}

// round 9
// speedup vs baseline: 1.1719x; 1.0402x over previous
#include <cuda_runtime.h>

#define BB   8
#define TT   48
#define CC   684
#define HH   16
#define WWD  64
#define HWN  1024
#define HIDN 256
#define AA   512
#define VV   111
#define LOCN 432
#define NBLK 128

typedef unsigned long long u64;

// ---------------- device scratch (static; no allocation) ----------------
__device__ unsigned g_barcnt;
__device__ float g_mask2[BB*HWN];
__device__ float g_avg[BB*CC];
__device__ float g_hidden[2*BB*HIDN];  // double-buffered by step parity
__device__ float g_locw[BB*HIDN];
__device__ float g_query[BB*AA];
__device__ float g_et[BB*HIDN];
__device__ float g_alpha_sum[BB*HWN];
__device__ float g_energy[BB*HWN];
__device__ float g_ctx[BB*CC];
__device__ float g_gpart[BB*16*6*HIDN];
__device__ float g_opart[BB*4*HIDN];
__device__ float g_ipart[64*HIDN];
__device__ float g_lpart[64*HIDN];
__device__ float2 g_Mp[121*256];       // paired (M[p][a], M[p][a+256])
__device__ float g_KfT[CC*AA];         // K_feat transposed [c][a]
__device__ float g_WihT[HIDN*768];     // [i][gate_j]
__device__ float g_WhhT[HIDN*768];
__device__ float g_trans[(size_t)BB*HWN*AA]; // 16.7 MB, L2-resident

__device__ __forceinline__ float wred(float v){
    #pragma unroll
    for (int o=16;o;o>>=1) v += __shfl_xor_sync(0xFFFFFFFFu, v, o);
    return v;
}
__device__ __forceinline__ float ftanh(float x){
    return 1.f - __fdividef(2.f, __expf(2.f*x) + 1.f);
}
__device__ __forceinline__ float fsig(float x){
    return __fdividef(1.f, 1.f + __expf(-x));
}
__device__ __forceinline__ u64 ffma2(u64 a, u64 b, u64 c){
    u64 d;
    asm("fma.rn.f32x2 %0, %1, %2, %3;" : "=l"(d) : "l"(a), "l"(b), "l"(c));
    return d;
}
__device__ __forceinline__ u64 pack2(float x, float y){
    u64 d; asm("mov.b64 %0, {%1, %2};" : "=l"(d) : "f"(x), "f"(y)); return d;
}
__device__ __forceinline__ void unpack2(u64 v, float& x, float& y){
    asm("mov.b64 {%0, %1}, %2;" : "=f"(x), "=f"(y) : "l"(v));
}

// grid-wide barrier (canonical ordering; validated in rounds 5-7)
__device__ __forceinline__ void gsync(unsigned &target){
    __threadfence();
    __syncthreads();
    target += NBLK;
    if (threadIdx.x == 0){
        atomicAdd(&g_barcnt, 1u);
        unsigned v;
        do {
            asm volatile("ld.acquire.gpu.u32 %0, [%1];" : "=r"(v) : "l"(&g_barcnt) : "memory");
        } while (v < target);
    }
    __syncthreads();
}

// ---------------- setup kernel 1: transposes + fused coverage matrix ----------------
__global__ void k_prep(const float* __restrict__ W_ih,
                       const float* __restrict__ W_hh,
                       const float* __restrict__ K_feat,
                       const float* __restrict__ K_cov,
                       const float* __restrict__ W_cov){
    int bx = blockIdx.x, tid = threadIdx.x;
    if (bx < 1368){
        int i = bx*256 + tid;
        if (i < 768*256){
            int r = i/256, c = i%256;
            g_WihT[c*768 + r] = W_ih[i];
            g_WhhT[c*768 + r] = W_hh[i];
        }
        if (i < 512*684){
            int a = i/684, c = i%684;
            g_KfT[c*512 + a] = K_feat[i];
        }
    } else {
        int p = bx - 1368;   // 0..120
        float s0 = 0.f, s1 = 0.f;
        #pragma unroll 4
        for (int c=0;c<512;c++){
            float k = K_cov[c*121 + p];
            s0 += k * W_cov[c*512 + tid];
            s1 += k * W_cov[c*512 + 256 + tid];
        }
        g_Mp[p*256 + tid] = make_float2(s0, s1);
    }
}

// ---------------- setup kernel 2: mask + avg + zeroing + barrier reset ----------------
__global__ void __launch_bounds__(256) k_avgmask(const float* __restrict__ imask,
                                                 const float* __restrict__ cnn){
    int slice = blockIdx.x, b = blockIdx.y;
    int tid = threadIdx.x, wid = tid>>5, lane = tid&31;
    __shared__ float msh[HWN];
    __shared__ float sred[8];
    float s = 0.f;
    #pragma unroll
    for (int k=0;k<4;k++){
        int hw = tid + 256*k;
        int h = hw >> 6, w = hw & 63;
        float v = imask[(size_t)b*262144 + (size_t)(h*16)*1024 + w*16];
        msh[hw] = v; s += v;
        if (slice == 0){
            g_mask2[b*HWN + hw] = v;
            g_alpha_sum[b*HWN + hw] = 0.f;
        }
    }
    if (slice == 0 && b == 0 && tid == 0) g_barcnt = 0u;
    s = wred(s);
    if (lane == 0) sred[wid] = s;
    __syncthreads();
    float tot = 0.f;
    #pragma unroll
    for (int i=0;i<8;i++) tot += sred[i];
    float inv = __fdividef(1.f, tot);
    int c0 = slice*86, cend = min(CC, c0+86);
    for (int c=c0+wid;c<cend;c+=8){
        const float* p = cnn + (size_t)(b*CC + c)*HWN;
        float acc = 0.f;
        #pragma unroll
        for (int m=0;m<32;m++) acc += msh[lane + 32*m] * p[lane + 32*m];
        acc = wred(acc);
        if (lane == 0) g_avg[b*CC + c] = acc*inv;
    }
}

// ---------------- setup kernel 3: one-time 1x1 conv (512 blocks, 16-pixel tiles) ----------------
__global__ void __launch_bounds__(256) k_trans(const float* __restrict__ cnn,
                                               const float* __restrict__ b_feat){
    int w0 = blockIdx.x*16, h = blockIdx.y, b = blockIdx.z;
    int tid = threadIdx.x;
    __shared__ __align__(16) float X[64][16];
    u64 acc0[8], acc1[8];
    #pragma unroll
    for (int i=0;i<8;i++){ acc0[i]=0ull; acc1[i]=0ull; }
    for (int c0=0;c0<CC;c0+=64){
        int nc = min(64, CC-c0);
        __syncthreads();
        for (int idx=tid; idx<nc*16; idx+=256){
            int cc = idx>>4, pix = idx&15;
            X[cc][pix] = cnn[(size_t)(b*CC + c0+cc)*HWN + h*WWD + w0 + pix];
        }
        __syncthreads();
        for (int cc=0; cc<nc; cc++){
            float k0 = g_KfT[(c0+cc)*AA + tid];
            float k1 = g_KfT[(c0+cc)*AA + 256 + tid];
            u64 k0p = pack2(k0,k0), k1p = pack2(k1,k1);
            #pragma unroll
            for (int k=0;k<8;k++){
                u64 x = *(const u64*)&X[cc][2*k];
                acc0[k] = ffma2(x, k0p, acc0[k]);
                acc1[k] = ffma2(x, k1p, acc1[k]);
            }
        }
    }
    float bf0 = b_feat[tid], bf1 = b_feat[256+tid];
    #pragma unroll
    for (int k=0;k<8;k++){
        float a0x,a0y,a1x,a1y;
        unpack2(acc0[k], a0x, a0y);
        unpack2(acc1[k], a1x, a1y);
        size_t gp0 = (size_t)((b*HH + h)*WWD + w0 + 2*k)*AA;
        size_t gp1 = gp0 + AA;
        g_trans[gp0 + tid]       = a0x + bf0;
        g_trans[gp0 + 256 + tid] = a1x + bf1;
        g_trans[gp1 + tid]       = a0y + bf0;
        g_trans[gp1 + 256 + tid] = a1y + bf1;
    }
}

// ---------------- persistent scan kernel ----------------
__global__ void __launch_bounds__(256) k_persist(
    const int*   __restrict__ labels,  const float* __restrict__ emb,
    const float* __restrict__ b_ih,    const float* __restrict__ b_hh,
    const float* __restrict__ W_q,     const float* __restrict__ b_q,
    const float* __restrict__ w_alpha, const float* __restrict__ b_alpha,
    const float* __restrict__ cnn,
    const float* __restrict__ W_state, const float* __restrict__ b_state,
    const float* __restrict__ W_emb,   const float* __restrict__ b_emb,
    const float* __restrict__ W_ctx,   const float* __restrict__ b_ctx,
    const float* __restrict__ W_out,   const float* __restrict__ b_out,
    const float* __restrict__ W_init,  const float* __restrict__ b_init,
    const float* __restrict__ locp,    const float* __restrict__ W_loc,
    const float* __restrict__ b_loc,
    float* __restrict__ probs_out, float* __restrict__ alphas_out,
    float* __restrict__ ctxs_out,  float* __restrict__ outs_out){

    int blk = blockIdx.x;
    int tid = threadIdx.x, wid = tid>>5, lane = tid&31;
    unsigned bar = 0;

    __shared__ __align__(16) float s_part[32][256];  // energy partials
    __shared__ __align__(8)  u64   s_nbd[11][42];    // duplicated-pair neighborhood
    __shared__ float s_am[HWN];
    __shared__ float s_vals[304];
    __shared__ float s_red[8];
    __shared__ float s_bc[2];

    // ---- P1: init-state partials (all 128 blocks) ----
    if (blk < 64){
        int b = blk>>3, sl = blk&7;
        int c0 = sl*86, n = min(CC, c0+86) - c0;
        for (int i=tid;i<n;i+=256) s_vals[i] = g_avg[b*CC + c0 + i];
        __syncthreads();
        float p = 0.f;
        for (int rr=0; rr<n; rr++) p += s_vals[rr]*W_init[(c0+rr)*HIDN + tid];
        __stcg(&g_ipart[(b*8 + sl)*HIDN + tid], p);
    } else {
        int b = (blk-64)>>3, sl = (blk-64)&7;
        int l0 = sl*54;
        for (int i=tid;i<54;i+=256) s_vals[i] = locp[b*LOCN + l0 + i];
        __syncthreads();
        float p = 0.f;
        #pragma unroll 2
        for (int rr=0; rr<54; rr++) p += s_vals[rr]*W_loc[(l0+rr)*HIDN + tid];
        __stcg(&g_lpart[(b*8 + sl)*HIDN + tid], p);
    }
    gsync(bar);

    // ---- P2: combine -> hidden0 (buffer 0), locw (8 blocks) ----
    if (blk < 8){
        int b = blk, j = tid;
        float h0 = b_init[j];
        float lw = b_loc[j];
        #pragma unroll
        for (int p=0;p<8;p++){
            h0 += __ldcg(&g_ipart[(b*8 + p)*HIDN + j]);
            lw += __ldcg(&g_lpart[(b*8 + p)*HIDN + j]);
        }
        __stcg(&g_hidden[b*HIDN + j], ftanh(h0));
        __stcg(&g_locw[b*HIDN + j], lw);
    }
    gsync(bar);

    // ======== scan ========
    for (int t = 0; t < TT; t++){
        int hcur = (t & 1) * BB*HIDN;
        int hnxt = ((t+1) & 1) * BB*HIDN;
        __syncthreads();   // protect s_vals reuse vs trailing D2 of prev step

        // ---- A1: GRU gate partials (all 128 blocks; (b, part16)) ----
        {
            int b = blk >> 4, part = blk & 15;
            int tok = (t == 0) ? 1 : labels[b*TT + t - 1];
            if (tid < 16)       s_vals[tid] = emb[tok*HIDN + part*16 + tid];
            else if (tid < 32)  s_vals[tid] = __ldcg(&g_hidden[hcur + b*HIDN + part*16 + tid - 16]);
            __syncthreads();
            int j = tid;
            float p0=0.f,p1=0.f,p2=0.f,p3=0.f,p4=0.f,p5=0.f;
            #pragma unroll
            for (int ii=0; ii<16; ii++){
                int i = part*16 + ii;
                float e = s_vals[ii], hh = s_vals[16+ii];
                const float* wi = &g_WihT[i*768];
                const float* wh = &g_WhhT[i*768];
                p0 += e*wi[j];      p1 += e*wi[256+j];  p2 += e*wi[512+j];
                p3 += hh*wh[j];     p4 += hh*wh[256+j]; p5 += hh*wh[512+j];
            }
            float* gp = &g_gpart[(b*16 + part)*6*HIDN];
            __stcg(&gp[j], p0);      __stcg(&gp[256+j], p1);  __stcg(&gp[512+j], p2);
            __stcg(&gp[768+j], p3);  __stcg(&gp[1024+j], p4); __stcg(&gp[1280+j], p5);
        }
        gsync(bar);

        // ---- A23: combine (redundant x2) + query (16 blocks; (b, half)) ----
        if (blk < 16){
            int b = blk >> 1, half = blk & 1;
            int j = tid;
            int tok = (t == 0) ? 1 : labels[b*TT + t - 1];
            float a0=b_ih[j], a1=b_ih[256+j], a2=b_ih[512+j];
            float a3=b_hh[j], a4=b_hh[256+j], a5=b_hh[512+j];
            #pragma unroll
            for (int p=0;p<16;p++){
                const float* gp = &g_gpart[(b*16 + p)*6*HIDN];
                a0 += __ldcg(&gp[j]);      a1 += __ldcg(&gp[256+j]);  a2 += __ldcg(&gp[512+j]);
                a3 += __ldcg(&gp[768+j]);  a4 += __ldcg(&gp[1024+j]); a5 += __ldcg(&gp[1280+j]);
            }
            float r = fsig(a0 + a3);
            float z = fsig(a1 + a4);
            float n = ftanh(a2 + r*a5);
            float hv = __ldcg(&g_hidden[hcur + b*HIDN + j]);
            float hn = (1.f - z)*n + z*hv;
            if (half == 0){
                __stcg(&g_hidden[hnxt + b*HIDN + j], hn);
                __stcg(&g_et[b*HIDN + j], emb[tok*HIDN + j]);
            }
            s_vals[j] = hn;
            __syncthreads();
            int j2 = half*256 + tid;
            float q = b_q[j2];
            #pragma unroll 8
            for (int i=0;i<HIDN;i++) q += s_vals[i]*W_q[i*AA + j2];
            __stcg(&g_query[b*AA + j2], q);
        }
        gsync(bar);

        // ---- B: coverage-conv + energy, FFMA2 alpha-pair packing ----
        {
            int b = blk >> 4, h = blk & 15;
            float q0 = __ldcg(&g_query[b*AA + tid]);
            float q1 = __ldcg(&g_query[b*AA + 256 + tid]);
            float wa0 = w_alpha[tid], wa1 = w_alpha[256 + tid];
            float ba = b_alpha[0];
            for (int tile=0; tile<2; tile++){
                int w0 = tile*32;
                __syncthreads();
                for (int idx=tid; idx<11*42; idx+=256){
                    int r = idx/42, cc = idx%42;
                    int gh = h - 5 + r, gw = w0 - 5 + cc;
                    float v = 0.f;
                    if (gh >= 0 && gh < HH && gw >= 0 && gw < WWD)
                        v = __ldcg(&g_alpha_sum[b*HWN + gh*WWD + gw]);
                    s_nbd[r][cc] = pack2(v, v);
                }
                __syncthreads();
                u64 acc[32];
                #pragma unroll
                for (int i=0;i<32;i++) acc[i]=0ull;
                #pragma unroll 1
                for (int py=0; py<11; py++){
                    u64 mp[11];
                    #pragma unroll
                    for (int px=0;px<11;px++){
                        float2 m2 = g_Mp[(py*11 + px)*256 + tid];
                        mp[px] = pack2(m2.x, m2.y);
                    }
                    #pragma unroll
                    for (int px=0; px<11; px++){
                        #pragma unroll
                        for (int pix=0;pix<32;pix++){
                            acc[pix] = ffma2(s_nbd[py][px+pix], mp[px], acc[pix]);
                        }
                    }
                }
                size_t gbase = (size_t)((b*HH + h)*WWD + w0)*AA + tid;
                #pragma unroll
                for (int pix=0;pix<32;pix++){
                    float a0, a1;
                    unpack2(acc[pix], a0, a1);
                    float s0 = ftanh(q0 + g_trans[gbase + (size_t)pix*AA]       + a0);
                    float s1 = ftanh(q1 + g_trans[gbase + (size_t)pix*AA + 256] + a1);
                    s_part[pix][tid] = wa0*s0 + wa1*s1;
                }
                __syncthreads();
                #pragma unroll
                for (int k=0;k<4;k++){
                    int pix = wid*4 + k;
                    float s = 0.f;
                    #pragma unroll
                    for (int m=0;m<8;m++) s += s_part[pix][lane + 32*m];
                    s = wred(s);
                    if (lane == 0) __stcg(&g_energy[b*HWN + h*WWD + w0 + pix], s + ba);
                }
            }
        }
        gsync(bar);

        // ---- C: softmax (redundant) + ctx (all 128; (b, chunk16)) ----
        {
            int b = blk >> 4, chunk = blk & 15;
            float mx = -1e30f;
            #pragma unroll
            for (int m=0;m<8;m++){
                float4 e4v = __ldcg((const float4*)&g_energy[tid*4 + 1024*m]);
                mx = fmaxf(mx, fmaxf(fmaxf(e4v.x, e4v.y), fmaxf(e4v.z, e4v.w)));
            }
            #pragma unroll
            for (int o=16;o;o>>=1) mx = fmaxf(mx, __shfl_xor_sync(0xFFFFFFFFu, mx, o));
            if (lane == 0) s_red[wid] = mx;
            __syncthreads();
            if (tid == 0){
                float m2 = s_red[0];
                #pragma unroll
                for (int i=1;i<8;i++) m2 = fmaxf(m2, s_red[i]);
                s_bc[0] = m2;
            }
            __syncthreads();
            mx = s_bc[0];
            float e4[4]; float loc = 0.f;
            int base = b*HWN + tid*4;
            float4 ein = __ldcg((const float4*)&g_energy[base]);
            float4 msk = *(const float4*)&g_mask2[base];
            e4[0] = __expf(ein.x - mx)*msk.x;
            e4[1] = __expf(ein.y - mx)*msk.y;
            e4[2] = __expf(ein.z - mx)*msk.z;
            e4[3] = __expf(ein.w - mx)*msk.w;
            loc = e4[0]+e4[1]+e4[2]+e4[3];
            loc = wred(loc);
            __syncthreads();
            if (lane == 0) s_red[wid] = loc;
            __syncthreads();
            if (tid == 0){
                float s = 0.f;
                #pragma unroll
                for (int i=0;i<8;i++) s += s_red[i];
                s_bc[1] = __fdividef(1.f, s + 1e-10f);
            }
            __syncthreads();
            float inv = s_bc[1];
            #pragma unroll
            for (int k=0;k<4;k++){
                float a = e4[k]*inv;
                int hw = tid*4 + k;
                s_am[hw] = (a > 0.02f) ? a : 0.f;
                if (chunk == 0){
                    alphas_out[(size_t)(b*TT + t)*HWN + hw] = a;
                    float as = __ldcg(&g_alpha_sum[b*HWN + hw]) + a;
                    __stcg(&g_alpha_sum[b*HWN + hw], as);
                }
            }
            __syncthreads();
            int c0 = chunk*43, cend = min(CC, c0+43);
            for (int c = c0 + wid; c < cend; c += 8){
                const float* p = cnn + (size_t)(b*CC + c)*HWN;
                float s = 0.f;
                #pragma unroll
                for (int m=0;m<8;m++){
                    float4 a4 = *(const float4*)&s_am[lane*4 + 128*m];
                    float4 p4 = *(const float4*)&p[lane*4 + 128*m];
                    s += a4.x*p4.x + a4.y*p4.y + a4.z*p4.z + a4.w*p4.w;
                }
                s = wred(s);
                if (lane == 0){
                    __stcg(&g_ctx[b*CC + c], s);
                    ctxs_out[(size_t)t*BB*CC + b*CC + c] = s;
                }
            }
        }
        gsync(bar);

        // ---- D1: out_state partials (32 blocks; (b, part4); 299 rows each) ----
        if (blk < 32){
            int b = blk >> 2, part = blk & 3;
            int lo = part*299, hi = lo + 299;
            for (int rr=tid; rr<299; rr+=256){
                int r = lo + rr;
                float v;
                if (r < 256)      v = __ldcg(&g_hidden[hnxt + b*HIDN + r]);
                else if (r < 512) v = __ldcg(&g_et[b*HIDN + r - 256]);
                else              v = __ldcg(&g_ctx[b*CC + r - 512]);
                s_vals[rr] = v;
            }
            __syncthreads();
            int j = tid;
            float s = 0.f;
            int r = lo;
            int e1 = min(hi, 256);
            #pragma unroll 4
            for (; r < e1; r++) s += s_vals[r-lo]*W_state[r*HIDN + j];
            r = max(lo, 256);
            int e2 = min(hi, 512);
            #pragma unroll 4
            for (; r < e2; r++) s += s_vals[r-lo]*W_emb[(r-256)*HIDN + j];
            r = max(lo, 512);
            #pragma unroll 4
            for (; r < hi; r++) s += s_vals[r-lo]*W_ctx[(r-512)*HIDN + j];
            __stcg(&g_opart[(b*4 + part)*HIDN + j], s);
        }
        gsync(bar);

        // ---- D2: maxout + vocab projection (8 blocks); overlaps next A1 ----
        if (blk < 8){
            int b = blk, j = tid;
            float s = b_state[j] + b_emb[j] + b_ctx[j];
            #pragma unroll
            for (int p=0;p<4;p++) s += __ldcg(&g_opart[(b*4 + p)*HIDN + j]);
            s = fmaxf(s, __ldcg(&g_locw[b*HIDN + j]));
            outs_out[(size_t)t*BB*HIDN + b*HIDN + j] = s;
            s_vals[j] = s;
            __syncthreads();
            if (j < VV){
                float pr = b_out[j];
                #pragma unroll 8
                for (int i=0;i<HIDN;i++) pr += s_vals[i]*W_out[i*VV + j];
                probs_out[(size_t)(b*TT + t)*VV + j] = pr;
            }
        }
        // no gsync: next A1 only writes g_gpart, untouched by D2; s_vals
        // reuse is protected by the __syncthreads at loop top.
    }
}

// ---------------- launch ----------------
extern "C" void kernel_launch(void* const* d_in, const int* in_sizes, int n_in,
                              void* d_out, int out_size){
    const float* cnn     = (const float*)d_in[0];
    const int*   labels  = (const int*  )d_in[1];
    const float* locp    = (const float*)d_in[2];
    const float* imask   = (const float*)d_in[3];
    const float* W_init  = (const float*)d_in[5];
    const float* b_init  = (const float*)d_in[6];
    const float* emb     = (const float*)d_in[7];
    const float* W_ih    = (const float*)d_in[8];
    const float* W_hh    = (const float*)d_in[9];
    const float* b_ih    = (const float*)d_in[10];
    const float* b_hh    = (const float*)d_in[11];
    const float* W_q     = (const float*)d_in[12];
    const float* b_q     = (const float*)d_in[13];
    const float* K_cov   = (const float*)d_in[14];
    const float* W_cov   = (const float*)d_in[15];
    const float* w_alpha = (const float*)d_in[16];
    const float* b_alpha = (const float*)d_in[17];
    const float* K_feat  = (const float*)d_in[18];
    const float* b_feat  = (const float*)d_in[19];
    const float* W_state = (const float*)d_in[20];
    const float* b_state = (const float*)d_in[21];
    const float* W_emb   = (const float*)d_in[22];
    const float* b_emb   = (const float*)d_in[23];
    const float* W_ctx   = (const float*)d_in[24];
    const float* b_ctx   = (const float*)d_in[25];
    const float* W_out   = (const float*)d_in[26];
    const float* b_out   = (const float*)d_in[27];
    const float* W_loc   = (const float*)d_in[28];
    const float* b_loc   = (const float*)d_in[29];

    float* out        = (float*)d_out;
    float* probs_out  = out;                                   // B*T*V
    float* alphas_out = probs_out + (size_t)BB*TT*VV;          // B*T*H*W
    float* ctxs_out   = alphas_out + (size_t)BB*TT*HWN;        // T*B*C
    float* outs_out   = ctxs_out + (size_t)TT*BB*CC;           // T*B*HID

    k_prep<<<1489, 256>>>(W_ih, W_hh, K_feat, K_cov, W_cov);
    k_avgmask<<<dim3(8, BB), 256>>>(imask, cnn);
    k_trans<<<dim3(4, HH, BB), 256>>>(cnn, b_feat);

    k_persist<<<NBLK, 256>>>(labels, emb, b_ih, b_hh, W_q, b_q,
                             w_alpha, b_alpha, cnn,
                             W_state, b_state, W_emb, b_emb,
                             W_ctx, b_ctx, W_out, b_out,
                             W_init, b_init, locp, W_loc, b_loc,
                             probs_out, alphas_out, ctxs_out, outs_out);
    (void)in_sizes; (void)n_in; (void)out_size;
}

// round 10
// speedup vs baseline: 1.7256x; 1.4725x over previous
#include <cuda_runtime.h>

#define BB   8
#define TT   48
#define CC   684
#define HH   16
#define WWD  64
#define HWN  1024
#define HIDN 256
#define AA   512
#define VV   111
#define LOCN 432
#define NBLK 128

typedef unsigned long long u64;

// ---------------- device scratch (static; no allocation) ----------------
__device__ unsigned g_barcnt;
__device__ float g_mask2[BB*HWN];
__device__ float g_avg[BB*CC];
__device__ float g_hidden[2*BB*HIDN];  // double-buffered by step parity
__device__ float g_locw[BB*HIDN];
__device__ float g_query[BB*AA];
__device__ float g_et[BB*HIDN];
__device__ float g_alpha_sum[BB*HWN];
__device__ float g_energy[BB*HWN];
__device__ float g_ctx[BB*CC];
__device__ float g_gpart[BB*16*6*HIDN];
__device__ float g_opart[BB*16*HIDN];  // 16 partials per batch now
__device__ float g_ipart[64*HIDN];
__device__ float g_lpart[64*HIDN];
__device__ float2 g_Mp[121*256];       // paired (M[p][a], M[p][a+256])
__device__ float g_KfT[CC*AA];         // K_feat transposed [c][a]
__device__ float g_WihT[HIDN*768];     // [i][gate_j]
__device__ float g_WhhT[HIDN*768];
__device__ float g_trans[(size_t)BB*HWN*AA]; // 16.7 MB, L2-resident

__device__ __forceinline__ float wred(float v){
    #pragma unroll
    for (int o=16;o;o>>=1) v += __shfl_xor_sync(0xFFFFFFFFu, v, o);
    return v;
}
__device__ __forceinline__ float ftanh(float x){
    return 1.f - __fdividef(2.f, __expf(2.f*x) + 1.f);
}
__device__ __forceinline__ float fsig(float x){
    return __fdividef(1.f, 1.f + __expf(-x));
}
__device__ __forceinline__ u64 ffma2(u64 a, u64 b, u64 c){
    u64 d;
    asm("fma.rn.f32x2 %0, %1, %2, %3;" : "=l"(d) : "l"(a), "l"(b), "l"(c));
    return d;
}
__device__ __forceinline__ u64 pack2(float x, float y){
    u64 d; asm("mov.b64 %0, {%1, %2};" : "=l"(d) : "f"(x), "f"(y)); return d;
}
__device__ __forceinline__ void unpack2(u64 v, float& x, float& y){
    asm("mov.b64 {%0, %1}, %2;" : "=f"(x), "=f"(y) : "l"(v));
}

// grid-wide barrier (canonical ordering; validated in rounds 5-9)
__device__ __forceinline__ void gsync(unsigned &target){
    __threadfence();
    __syncthreads();
    target += NBLK;
    if (threadIdx.x == 0){
        atomicAdd(&g_barcnt, 1u);
        unsigned v;
        do {
            asm volatile("ld.acquire.gpu.u32 %0, [%1];" : "=r"(v) : "l"(&g_barcnt) : "memory");
        } while (v < target);
    }
    __syncthreads();
}

// phase-B helpers: textual macros keep register arrays register-resident
#define LOAD_MP(mp, py) do { \
    _Pragma("unroll") \
    for (int px=0;px<11;px++){ \
        float2 m2 = g_Mp[((py)*11+px)*256 + tid]; \
        mp[px] = pack2(m2.x, m2.y); \
    } } while(0)

#define CONV_ROW(py, mp) do { \
    _Pragma("unroll") \
    for (int px=0;px<11;px++){ \
        _Pragma("unroll") \
        for (int pix=0;pix<32;pix++) \
            acc[pix] = ffma2(s_nbd[py][px+pix], mp[px], acc[pix]); \
    } } while(0)

// ---------------- setup kernel 1: transposes + fused coverage matrix ----------------
__global__ void k_prep(const float* __restrict__ W_ih,
                       const float* __restrict__ W_hh,
                       const float* __restrict__ K_feat,
                       const float* __restrict__ K_cov,
                       const float* __restrict__ W_cov){
    int bx = blockIdx.x, tid = threadIdx.x;
    if (bx < 1368){
        int i = bx*256 + tid;
        if (i < 768*256){
            int r = i/256, c = i%256;
            g_WihT[c*768 + r] = W_ih[i];
            g_WhhT[c*768 + r] = W_hh[i];
        }
        if (i < 512*684){
            int a = i/684, c = i%684;
            g_KfT[c*512 + a] = K_feat[i];
        }
    } else {
        int p = bx - 1368;   // 0..120
        float s0 = 0.f, s1 = 0.f;
        #pragma unroll 4
        for (int c=0;c<512;c++){
            float k = K_cov[c*121 + p];
            s0 += k * W_cov[c*512 + tid];
            s1 += k * W_cov[c*512 + 256 + tid];
        }
        g_Mp[p*256 + tid] = make_float2(s0, s1);
    }
}

// ---------------- setup kernel 2: mask + avg + zeroing + barrier reset ----------------
__global__ void __launch_bounds__(256) k_avgmask(const float* __restrict__ imask,
                                                 const float* __restrict__ cnn){
    int slice = blockIdx.x, b = blockIdx.y;
    int tid = threadIdx.x, wid = tid>>5, lane = tid&31;
    __shared__ float msh[HWN];
    __shared__ float sred[8];
    float s = 0.f;
    #pragma unroll
    for (int k=0;k<4;k++){
        int hw = tid + 256*k;
        int h = hw >> 6, w = hw & 63;
        float v = imask[(size_t)b*262144 + (size_t)(h*16)*1024 + w*16];
        msh[hw] = v; s += v;
        if (slice == 0){
            g_mask2[b*HWN + hw] = v;
            g_alpha_sum[b*HWN + hw] = 0.f;
        }
    }
    if (slice == 0 && b == 0 && tid == 0) g_barcnt = 0u;
    s = wred(s);
    if (lane == 0) sred[wid] = s;
    __syncthreads();
    float tot = 0.f;
    #pragma unroll
    for (int i=0;i<8;i++) tot += sred[i];
    float inv = __fdividef(1.f, tot);
    int c0 = slice*86, cend = min(CC, c0+86);
    for (int c=c0+wid;c<cend;c+=8){
        const float* p = cnn + (size_t)(b*CC + c)*HWN;
        float acc = 0.f;
        #pragma unroll
        for (int m=0;m<32;m++) acc += msh[lane + 32*m] * p[lane + 32*m];
        acc = wred(acc);
        if (lane == 0) g_avg[b*CC + c] = acc*inv;
    }
}

// ---------------- setup kernel 3: one-time 1x1 conv ----------------
__global__ void __launch_bounds__(256) k_trans(const float* __restrict__ cnn,
                                               const float* __restrict__ b_feat){
    int w0 = blockIdx.x*16, h = blockIdx.y, b = blockIdx.z;
    int tid = threadIdx.x;
    __shared__ __align__(16) float X[64][16];
    u64 acc0[8], acc1[8];
    #pragma unroll
    for (int i=0;i<8;i++){ acc0[i]=0ull; acc1[i]=0ull; }
    for (int c0=0;c0<CC;c0+=64){
        int nc = min(64, CC-c0);
        __syncthreads();
        for (int idx=tid; idx<nc*16; idx+=256){
            int cc = idx>>4, pix = idx&15;
            X[cc][pix] = cnn[(size_t)(b*CC + c0+cc)*HWN + h*WWD + w0 + pix];
        }
        __syncthreads();
        for (int cc=0; cc<nc; cc++){
            float k0 = g_KfT[(c0+cc)*AA + tid];
            float k1 = g_KfT[(c0+cc)*AA + 256 + tid];
            u64 k0p = pack2(k0,k0), k1p = pack2(k1,k1);
            #pragma unroll
            for (int k=0;k<8;k++){
                u64 x = *(const u64*)&X[cc][2*k];
                acc0[k] = ffma2(x, k0p, acc0[k]);
                acc1[k] = ffma2(x, k1p, acc1[k]);
            }
        }
    }
    float bf0 = b_feat[tid], bf1 = b_feat[256+tid];
    #pragma unroll
    for (int k=0;k<8;k++){
        float a0x,a0y,a1x,a1y;
        unpack2(acc0[k], a0x, a0y);
        unpack2(acc1[k], a1x, a1y);
        size_t gp0 = (size_t)((b*HH + h)*WWD + w0 + 2*k)*AA;
        size_t gp1 = gp0 + AA;
        g_trans[gp0 + tid]       = a0x + bf0;
        g_trans[gp0 + 256 + tid] = a1x + bf1;
        g_trans[gp1 + tid]       = a0y + bf0;
        g_trans[gp1 + 256 + tid] = a1y + bf1;
    }
}

// ---------------- persistent scan kernel ----------------
__global__ void __launch_bounds__(256) k_persist(
    const int*   __restrict__ labels,  const float* __restrict__ emb,
    const float* __restrict__ b_ih,    const float* __restrict__ b_hh,
    const float* __restrict__ W_q,     const float* __restrict__ b_q,
    const float* __restrict__ w_alpha, const float* __restrict__ b_alpha,
    const float* __restrict__ cnn,
    const float* __restrict__ W_state, const float* __restrict__ b_state,
    const float* __restrict__ W_emb,   const float* __restrict__ b_emb,
    const float* __restrict__ W_ctx,   const float* __restrict__ b_ctx,
    const float* __restrict__ W_out,   const float* __restrict__ b_out,
    const float* __restrict__ W_init,  const float* __restrict__ b_init,
    const float* __restrict__ locp,    const float* __restrict__ W_loc,
    const float* __restrict__ b_loc,
    float* __restrict__ probs_out, float* __restrict__ alphas_out,
    float* __restrict__ ctxs_out,  float* __restrict__ outs_out){

    int blk = blockIdx.x;
    int tid = threadIdx.x, wid = tid>>5, lane = tid&31;
    unsigned bar = 0;

    __shared__ __align__(16) float s_part[32][256];  // energy partials
    __shared__ __align__(8)  u64   s_nbd[11][42];    // duplicated-pair neighborhood
    __shared__ float s_am[HWN];
    __shared__ float s_vals[304];
    __shared__ float s_red[8];
    __shared__ float s_bc[2];

    // ---- P1: init-state partials (all 128 blocks) ----
    if (blk < 64){
        int b = blk>>3, sl = blk&7;
        int c0 = sl*86, n = min(CC, c0+86) - c0;
        for (int i=tid;i<n;i+=256) s_vals[i] = g_avg[b*CC + c0 + i];
        __syncthreads();
        float p = 0.f;
        for (int rr=0; rr<n; rr++) p += s_vals[rr]*W_init[(c0+rr)*HIDN + tid];
        __stcg(&g_ipart[(b*8 + sl)*HIDN + tid], p);
    } else {
        int b = (blk-64)>>3, sl = (blk-64)&7;
        int l0 = sl*54;
        for (int i=tid;i<54;i+=256) s_vals[i] = locp[b*LOCN + l0 + i];
        __syncthreads();
        float p = 0.f;
        #pragma unroll 2
        for (int rr=0; rr<54; rr++) p += s_vals[rr]*W_loc[(l0+rr)*HIDN + tid];
        __stcg(&g_lpart[(b*8 + sl)*HIDN + tid], p);
    }
    gsync(bar);

    // ---- P2: combine -> hidden0 (buffer 0), locw (8 blocks) ----
    if (blk < 8){
        int b = blk, j = tid;
        float h0 = b_init[j];
        float lw = b_loc[j];
        #pragma unroll
        for (int p=0;p<8;p++){
            h0 += __ldcg(&g_ipart[(b*8 + p)*HIDN + j]);
            lw += __ldcg(&g_lpart[(b*8 + p)*HIDN + j]);
        }
        __stcg(&g_hidden[b*HIDN + j], ftanh(h0));
        __stcg(&g_locw[b*HIDN + j], lw);
    }
    gsync(bar);

    // ======== scan ========
    for (int t = 0; t < TT; t++){
        int hcur = (t & 1) * BB*HIDN;
        int hnxt = ((t+1) & 1) * BB*HIDN;
        __syncthreads();   // protect s_vals reuse vs trailing D2 of prev step

        // ---- A1: GRU gate partials (all 128 blocks; (b, part16)) ----
        {
            int b = blk >> 4, part = blk & 15;
            int tok = (t == 0) ? 1 : labels[b*TT + t - 1];
            if (tid < 16)       s_vals[tid] = emb[tok*HIDN + part*16 + tid];
            else if (tid < 32)  s_vals[tid] = __ldcg(&g_hidden[hcur + b*HIDN + part*16 + tid - 16]);
            __syncthreads();
            int j = tid;
            float p0=0.f,p1=0.f,p2=0.f,p3=0.f,p4=0.f,p5=0.f;
            #pragma unroll
            for (int ii=0; ii<16; ii++){
                int i = part*16 + ii;
                float e = s_vals[ii], hh = s_vals[16+ii];
                const float* wi = &g_WihT[i*768];
                const float* wh = &g_WhhT[i*768];
                p0 += e*wi[j];      p1 += e*wi[256+j];  p2 += e*wi[512+j];
                p3 += hh*wh[j];     p4 += hh*wh[256+j]; p5 += hh*wh[512+j];
            }
            float* gp = &g_gpart[(b*16 + part)*6*HIDN];
            __stcg(&gp[j], p0);      __stcg(&gp[256+j], p1);  __stcg(&gp[512+j], p2);
            __stcg(&gp[768+j], p3);  __stcg(&gp[1024+j], p4); __stcg(&gp[1280+j], p5);
        }
        gsync(bar);

        // ---- A23: combine (redundant x2) + query (16 blocks; (b, half)) ----
        if (blk < 16){
            int b = blk >> 1, half = blk & 1;
            int j = tid;
            int tok = (t == 0) ? 1 : labels[b*TT + t - 1];
            float a0=b_ih[j], a1=b_ih[256+j], a2=b_ih[512+j];
            float a3=b_hh[j], a4=b_hh[256+j], a5=b_hh[512+j];
            #pragma unroll
            for (int p=0;p<16;p++){
                const float* gp = &g_gpart[(b*16 + p)*6*HIDN];
                a0 += __ldcg(&gp[j]);      a1 += __ldcg(&gp[256+j]);  a2 += __ldcg(&gp[512+j]);
                a3 += __ldcg(&gp[768+j]);  a4 += __ldcg(&gp[1024+j]); a5 += __ldcg(&gp[1280+j]);
            }
            float r = fsig(a0 + a3);
            float z = fsig(a1 + a4);
            float n = ftanh(a2 + r*a5);
            float hv = __ldcg(&g_hidden[hcur + b*HIDN + j]);
            float hn = (1.f - z)*n + z*hv;
            if (half == 0){
                __stcg(&g_hidden[hnxt + b*HIDN + j], hn);
                __stcg(&g_et[b*HIDN + j], emb[tok*HIDN + j]);
            }
            s_vals[j] = hn;
            __syncthreads();
            int j2 = half*256 + tid;
            float q0=0.f, q1=0.f, q2=0.f, q3=0.f;
            #pragma unroll
            for (int i=0;i<HIDN;i+=4){
                q0 += s_vals[i  ]*W_q[(i  )*AA + j2];
                q1 += s_vals[i+1]*W_q[(i+1)*AA + j2];
                q2 += s_vals[i+2]*W_q[(i+2)*AA + j2];
                q3 += s_vals[i+3]*W_q[(i+3)*AA + j2];
            }
            __stcg(&g_query[b*AA + j2], b_q[j2] + ((q0+q1)+(q2+q3)));
        }
        gsync(bar);

        // ---- B: coverage-conv + energy, FFMA2 + pipelined M prefetch ----
        {
            int b = blk >> 4, h = blk & 15;
            float q0 = __ldcg(&g_query[b*AA + tid]);
            float q1 = __ldcg(&g_query[b*AA + 256 + tid]);
            float wa0 = w_alpha[tid], wa1 = w_alpha[256 + tid];
            float ba = b_alpha[0];
            for (int tile=0; tile<2; tile++){
                int w0 = tile*32;
                __syncthreads();
                for (int idx=tid; idx<11*42; idx+=256){
                    int r = idx/42, cc = idx%42;
                    int gh = h - 5 + r, gw = w0 - 5 + cc;
                    float v = 0.f;
                    if (gh >= 0 && gh < HH && gw >= 0 && gw < WWD)
                        v = __ldcg(&g_alpha_sum[b*HWN + gh*WWD + gw]);
                    s_nbd[r][cc] = pack2(v, v);
                }
                __syncthreads();
                u64 acc[32];
                #pragma unroll
                for (int i=0;i<32;i++) acc[i]=0ull;
                // software-pipelined conv: rows 0..10, identical FMA order
                u64 mpA[11], mpB[11];
                LOAD_MP(mpA, 0);
                #pragma unroll 1
                for (int pyb=0; pyb<5; pyb++){
                    int py0 = 2*pyb;
                    LOAD_MP(mpB, py0+1);
                    CONV_ROW(py0, mpA);
                    LOAD_MP(mpA, py0+2);   // py0+2 <= 10 always
                    CONV_ROW(py0+1, mpB);
                }
                CONV_ROW(10, mpA);
                size_t gbase = (size_t)((b*HH + h)*WWD + w0)*AA + tid;
                #pragma unroll
                for (int pix=0;pix<32;pix++){
                    float a0, a1;
                    unpack2(acc[pix], a0, a1);
                    float s0 = ftanh(q0 + g_trans[gbase + (size_t)pix*AA]       + a0);
                    float s1 = ftanh(q1 + g_trans[gbase + (size_t)pix*AA + 256] + a1);
                    s_part[pix][tid] = wa0*s0 + wa1*s1;
                }
                __syncthreads();
                #pragma unroll
                for (int k=0;k<4;k++){
                    int pix = wid*4 + k;
                    float s = 0.f;
                    #pragma unroll
                    for (int m=0;m<8;m++) s += s_part[pix][lane + 32*m];
                    s = wred(s);
                    if (lane == 0) __stcg(&g_energy[b*HWN + h*WWD + w0 + pix], s + ba);
                }
            }
        }
        gsync(bar);

        // ---- C: softmax (redundant) + ctx (all 128; (b, chunk16)) ----
        {
            int b = blk >> 4, chunk = blk & 15;
            float mx = -1e30f;
            #pragma unroll
            for (int m=0;m<8;m++){
                float4 e4v = __ldcg((const float4*)&g_energy[tid*4 + 1024*m]);
                mx = fmaxf(mx, fmaxf(fmaxf(e4v.x, e4v.y), fmaxf(e4v.z, e4v.w)));
            }
            #pragma unroll
            for (int o=16;o;o>>=1) mx = fmaxf(mx, __shfl_xor_sync(0xFFFFFFFFu, mx, o));
            if (lane == 0) s_red[wid] = mx;
            __syncthreads();
            if (tid == 0){
                float m2 = s_red[0];
                #pragma unroll
                for (int i=1;i<8;i++) m2 = fmaxf(m2, s_red[i]);
                s_bc[0] = m2;
            }
            __syncthreads();
            mx = s_bc[0];
            float e4[4]; float loc = 0.f;
            int base = b*HWN + tid*4;
            float4 ein = __ldcg((const float4*)&g_energy[base]);
            float4 msk = *(const float4*)&g_mask2[base];
            e4[0] = __expf(ein.x - mx)*msk.x;
            e4[1] = __expf(ein.y - mx)*msk.y;
            e4[2] = __expf(ein.z - mx)*msk.z;
            e4[3] = __expf(ein.w - mx)*msk.w;
            loc = e4[0]+e4[1]+e4[2]+e4[3];
            loc = wred(loc);
            __syncthreads();
            if (lane == 0) s_red[wid] = loc;
            __syncthreads();
            if (tid == 0){
                float s = 0.f;
                #pragma unroll
                for (int i=0;i<8;i++) s += s_red[i];
                s_bc[1] = __fdividef(1.f, s + 1e-10f);
            }
            __syncthreads();
            float inv = s_bc[1];
            #pragma unroll
            for (int k=0;k<4;k++){
                float a = e4[k]*inv;
                int hw = tid*4 + k;
                s_am[hw] = (a > 0.02f) ? a : 0.f;
                if (chunk == 0){
                    alphas_out[(size_t)(b*TT + t)*HWN + hw] = a;
                    float as = __ldcg(&g_alpha_sum[b*HWN + hw]) + a;
                    __stcg(&g_alpha_sum[b*HWN + hw], as);
                }
            }
            __syncthreads();
            int c0 = chunk*43, cend = min(CC, c0+43);
            for (int c = c0 + wid; c < cend; c += 8){
                const float* p = cnn + (size_t)(b*CC + c)*HWN;
                float s = 0.f;
                #pragma unroll
                for (int m=0;m<8;m++){
                    float4 a4 = *(const float4*)&s_am[lane*4 + 128*m];
                    float4 p4 = *(const float4*)&p[lane*4 + 128*m];
                    s += a4.x*p4.x + a4.y*p4.y + a4.z*p4.z + a4.w*p4.w;
                }
                s = wred(s);
                if (lane == 0){
                    __stcg(&g_ctx[b*CC + c], s);
                    ctxs_out[(size_t)t*BB*CC + b*CC + c] = s;
                }
            }
        }
        gsync(bar);

        // ---- D1: out_state partials (ALL 128 blocks; (b, part16); 75 rows) ----
        {
            int b = blk >> 4, part = blk & 15;
            int lo = part*75, hi = min(1196, lo + 75);
            int n = hi - lo;
            for (int rr=tid; rr<n; rr+=256){
                int r = lo + rr;
                float v;
                if (r < 256)      v = __ldcg(&g_hidden[hnxt + b*HIDN + r]);
                else if (r < 512) v = __ldcg(&g_et[b*HIDN + r - 256]);
                else              v = __ldcg(&g_ctx[b*CC + r - 512]);
                s_vals[rr] = v;
            }
            __syncthreads();
            int j = tid;
            float s = 0.f;
            int r = lo;
            int e1 = min(hi, 256);
            #pragma unroll 8
            for (; r < e1; r++) s += s_vals[r-lo]*W_state[r*HIDN + j];
            r = max(lo, 256);
            int e2 = min(hi, 512);
            #pragma unroll 8
            for (; r < e2; r++) s += s_vals[r-lo]*W_emb[(r-256)*HIDN + j];
            r = max(lo, 512);
            #pragma unroll 8
            for (; r < hi; r++) s += s_vals[r-lo]*W_ctx[(r-512)*HIDN + j];
            __stcg(&g_opart[(b*16 + part)*HIDN + j], s);
        }
        gsync(bar);

        // ---- D2: maxout + vocab projection (8 blocks); overlaps next A1 ----
        if (blk < 8){
            int b = blk, j = tid;
            float s = b_state[j] + b_emb[j] + b_ctx[j];
            #pragma unroll
            for (int p=0;p<16;p++) s += __ldcg(&g_opart[(b*16 + p)*HIDN + j]);
            s = fmaxf(s, __ldcg(&g_locw[b*HIDN + j]));
            outs_out[(size_t)t*BB*HIDN + b*HIDN + j] = s;
            s_vals[j] = s;
            __syncthreads();
            if (j < VV){
                float p0=0.f, p1=0.f, p2=0.f, p3=0.f;
                #pragma unroll
                for (int i=0;i<HIDN;i+=4){
                    p0 += s_vals[i  ]*W_out[(i  )*VV + j];
                    p1 += s_vals[i+1]*W_out[(i+1)*VV + j];
                    p2 += s_vals[i+2]*W_out[(i+2)*VV + j];
                    p3 += s_vals[i+3]*W_out[(i+3)*VV + j];
                }
                probs_out[(size_t)(b*TT + t)*VV + j] = b_out[j] + ((p0+p1)+(p2+p3));
            }
        }
        // no gsync: next A1 only writes g_gpart, untouched by D2; s_vals
        // reuse is protected by the __syncthreads at loop top.
    }
}

// ---------------- launch ----------------
extern "C" void kernel_launch(void* const* d_in, const int* in_sizes, int n_in,
                              void* d_out, int out_size){
    const float* cnn     = (const float*)d_in[0];
    const int*   labels  = (const int*  )d_in[1];
    const float* locp    = (const float*)d_in[2];
    const float* imask   = (const float*)d_in[3];
    const float* W_init  = (const float*)d_in[5];
    const float* b_init  = (const float*)d_in[6];
    const float* emb     = (const float*)d_in[7];
    const float* W_ih    = (const float*)d_in[8];
    const float* W_hh    = (const float*)d_in[9];
    const float* b_ih    = (const float*)d_in[10];
    const float* b_hh    = (const float*)d_in[11];
    const float* W_q     = (const float*)d_in[12];
    const float* b_q     = (const float*)d_in[13];
    const float* K_cov   = (const float*)d_in[14];
    const float* W_cov   = (const float*)d_in[15];
    const float* w_alpha = (const float*)d_in[16];
    const float* b_alpha = (const float*)d_in[17];
    const float* K_feat  = (const float*)d_in[18];
    const float* b_feat  = (const float*)d_in[19];
    const float* W_state = (const float*)d_in[20];
    const float* b_state = (const float*)d_in[21];
    const float* W_emb   = (const float*)d_in[22];
    const float* b_emb   = (const float*)d_in[23];
    const float* W_ctx   = (const float*)d_in[24];
    const float* b_ctx   = (const float*)d_in[25];
    const float* W_out   = (const float*)d_in[26];
    const float* b_out   = (const float*)d_in[27];
    const float* W_loc   = (const float*)d_in[28];
    const float* b_loc   = (const float*)d_in[29];

    float* out        = (float*)d_out;
    float* probs_out  = out;                                   // B*T*V
    float* alphas_out = probs_out + (size_t)BB*TT*VV;          // B*T*H*W
    float* ctxs_out   = alphas_out + (size_t)BB*TT*HWN;        // T*B*C
    float* outs_out   = ctxs_out + (size_t)TT*BB*CC;           // T*B*HID

    k_prep<<<1489, 256>>>(W_ih, W_hh, K_feat, K_cov, W_cov);
    k_avgmask<<<dim3(8, BB), 256>>>(imask, cnn);
    k_trans<<<dim3(4, HH, BB), 256>>>(cnn, b_feat);

    k_persist<<<NBLK, 256>>>(labels, emb, b_ih, b_hh, W_q, b_q,
                             w_alpha, b_alpha, cnn,
                             W_state, b_state, W_emb, b_emb,
                             W_ctx, b_ctx, W_out, b_out,
                             W_init, b_init, locp, W_loc, b_loc,
                             probs_out, alphas_out, ctxs_out, outs_out);
    (void)in_sizes; (void)n_in; (void)out_size;
}

// round 11
// speedup vs baseline: 1.8195x; 1.0544x over previous
#include <cuda_runtime.h>

#define BB   8
#define TT   48
#define CC   684
#define HH   16
#define WWD  64
#define HWN  1024
#define HIDN 256
#define AA   512
#define VV   111
#define LOCN 432
#define NBLK 128

typedef unsigned long long u64;

// ---------------- device scratch (static; no allocation) ----------------
__device__ unsigned g_barcnt;
__device__ unsigned g_qcnt;            // query-ready flag (monotonic)
__device__ float g_mask2[BB*HWN];
__device__ float g_avg[BB*CC];
__device__ float g_hidden[2*BB*HIDN];  // double-buffered by step parity
__device__ float g_locw[BB*HIDN];
__device__ float g_query[BB*AA];
__device__ float g_et[BB*HIDN];
__device__ float g_alpha_sum[BB*HWN];
__device__ float g_energy[BB*HWN];
__device__ float g_bmax[NBLK];         // per-block energy max
__device__ float g_ctx[BB*CC];
__device__ float g_gpart[BB*16*6*HIDN];
__device__ float g_opart[BB*16*HIDN];
__device__ float g_ipart[64*HIDN];
__device__ float g_lpart[64*HIDN];
__device__ float2 g_Mp[121*256];       // paired (M[p][a], M[p][a+256])
__device__ float g_KfT[CC*AA];         // K_feat transposed [c][a]
__device__ float g_WihT[HIDN*768];     // [i][gate_j]
__device__ float g_WhhT[HIDN*768];
__device__ float g_trans[(size_t)BB*HWN*AA]; // 16.7 MB, L2-resident

__device__ __forceinline__ float wred(float v){
    #pragma unroll
    for (int o=16;o;o>>=1) v += __shfl_xor_sync(0xFFFFFFFFu, v, o);
    return v;
}
__device__ __forceinline__ float wredmax(float v){
    #pragma unroll
    for (int o=16;o;o>>=1) v = fmaxf(v, __shfl_xor_sync(0xFFFFFFFFu, v, o));
    return v;
}
__device__ __forceinline__ float ftanh(float x){
    return 1.f - __fdividef(2.f, __expf(2.f*x) + 1.f);
}
__device__ __forceinline__ float fsig(float x){
    return __fdividef(1.f, 1.f + __expf(-x));
}
__device__ __forceinline__ u64 ffma2(u64 a, u64 b, u64 c){
    u64 d;
    asm("fma.rn.f32x2 %0, %1, %2, %3;" : "=l"(d) : "l"(a), "l"(b), "l"(c));
    return d;
}
__device__ __forceinline__ u64 pack2(float x, float y){
    u64 d; asm("mov.b64 %0, {%1, %2};" : "=l"(d) : "f"(x), "f"(y)); return d;
}
__device__ __forceinline__ void unpack2(u64 v, float& x, float& y){
    asm("mov.b64 {%0, %1}, %2;" : "=f"(x), "=f"(y) : "l"(v));
}

// grid-wide barrier (canonical ordering; validated in rounds 5-10)
__device__ __forceinline__ void gsync(unsigned &target){
    __threadfence();
    __syncthreads();
    target += NBLK;
    if (threadIdx.x == 0){
        atomicAdd(&g_barcnt, 1u);
        unsigned v;
        do {
            asm volatile("ld.acquire.gpu.u32 %0, [%1];" : "=r"(v) : "l"(&g_barcnt) : "memory");
        } while (v < target);
    }
    __syncthreads();
}

// phase-B helpers: textual macros keep register arrays register-resident
#define LOAD_MP(mp, py) do { \
    _Pragma("unroll") \
    for (int px=0;px<11;px++){ \
        float2 m2 = g_Mp[((py)*11+px)*256 + tid]; \
        mp[px] = pack2(m2.x, m2.y); \
    } } while(0)

#define CONV_ROW(py, mp) do { \
    _Pragma("unroll") \
    for (int px=0;px<11;px++){ \
        _Pragma("unroll") \
        for (int pix=0;pix<32;pix++) \
            acc[pix] = ffma2(s_nbd[py][px+pix], mp[px], acc[pix]); \
    } } while(0)

// ---------------- setup kernel 1: transposes + fused coverage matrix ----------------
__global__ void k_prep(const float* __restrict__ W_ih,
                       const float* __restrict__ W_hh,
                       const float* __restrict__ K_feat,
                       const float* __restrict__ K_cov,
                       const float* __restrict__ W_cov){
    int bx = blockIdx.x, tid = threadIdx.x;
    if (bx < 1368){
        int i = bx*256 + tid;
        if (i < 768*256){
            int r = i/256, c = i%256;
            g_WihT[c*768 + r] = W_ih[i];
            g_WhhT[c*768 + r] = W_hh[i];
        }
        if (i < 512*684){
            int a = i/684, c = i%684;
            g_KfT[c*512 + a] = K_feat[i];
        }
    } else {
        int p = bx - 1368;   // 0..120
        float s0 = 0.f, s1 = 0.f;
        #pragma unroll 4
        for (int c=0;c<512;c++){
            float k = K_cov[c*121 + p];
            s0 += k * W_cov[c*512 + tid];
            s1 += k * W_cov[c*512 + 256 + tid];
        }
        g_Mp[p*256 + tid] = make_float2(s0, s1);
    }
}

// ---------------- setup kernel 2: mask + avg + zeroing + flag reset ----------------
__global__ void __launch_bounds__(256) k_avgmask(const float* __restrict__ imask,
                                                 const float* __restrict__ cnn){
    int slice = blockIdx.x, b = blockIdx.y;
    int tid = threadIdx.x, wid = tid>>5, lane = tid&31;
    __shared__ float msh[HWN];
    __shared__ float sred[8];
    float s = 0.f;
    #pragma unroll
    for (int k=0;k<4;k++){
        int hw = tid + 256*k;
        int h = hw >> 6, w = hw & 63;
        float v = imask[(size_t)b*262144 + (size_t)(h*16)*1024 + w*16];
        msh[hw] = v; s += v;
        if (slice == 0){
            g_mask2[b*HWN + hw] = v;
            g_alpha_sum[b*HWN + hw] = 0.f;
        }
    }
    if (slice == 0 && b == 0 && tid == 0){ g_barcnt = 0u; g_qcnt = 0u; }
    s = wred(s);
    if (lane == 0) sred[wid] = s;
    __syncthreads();
    float tot = 0.f;
    #pragma unroll
    for (int i=0;i<8;i++) tot += sred[i];
    float inv = __fdividef(1.f, tot);
    int c0 = slice*86, cend = min(CC, c0+86);
    for (int c=c0+wid;c<cend;c+=8){
        const float* p = cnn + (size_t)(b*CC + c)*HWN;
        float acc = 0.f;
        #pragma unroll
        for (int m=0;m<32;m++) acc += msh[lane + 32*m] * p[lane + 32*m];
        acc = wred(acc);
        if (lane == 0) g_avg[b*CC + c] = acc*inv;
    }
}

// ---------------- setup kernel 3: one-time 1x1 conv ----------------
__global__ void __launch_bounds__(256) k_trans(const float* __restrict__ cnn,
                                               const float* __restrict__ b_feat){
    int w0 = blockIdx.x*16, h = blockIdx.y, b = blockIdx.z;
    int tid = threadIdx.x;
    __shared__ __align__(16) float X[64][16];
    u64 acc0[8], acc1[8];
    #pragma unroll
    for (int i=0;i<8;i++){ acc0[i]=0ull; acc1[i]=0ull; }
    for (int c0=0;c0<CC;c0+=64){
        int nc = min(64, CC-c0);
        __syncthreads();
        for (int idx=tid; idx<nc*16; idx+=256){
            int cc = idx>>4, pix = idx&15;
            X[cc][pix] = cnn[(size_t)(b*CC + c0+cc)*HWN + h*WWD + w0 + pix];
        }
        __syncthreads();
        for (int cc=0; cc<nc; cc++){
            float k0 = g_KfT[(c0+cc)*AA + tid];
            float k1 = g_KfT[(c0+cc)*AA + 256 + tid];
            u64 k0p = pack2(k0,k0), k1p = pack2(k1,k1);
            #pragma unroll
            for (int k=0;k<8;k++){
                u64 x = *(const u64*)&X[cc][2*k];
                acc0[k] = ffma2(x, k0p, acc0[k]);
                acc1[k] = ffma2(x, k1p, acc1[k]);
            }
        }
    }
    float bf0 = b_feat[tid], bf1 = b_feat[256+tid];
    #pragma unroll
    for (int k=0;k<8;k++){
        float a0x,a0y,a1x,a1y;
        unpack2(acc0[k], a0x, a0y);
        unpack2(acc1[k], a1x, a1y);
        size_t gp0 = (size_t)((b*HH + h)*WWD + w0 + 2*k)*AA;
        size_t gp1 = gp0 + AA;
        g_trans[gp0 + tid]       = a0x + bf0;
        g_trans[gp0 + 256 + tid] = a1x + bf1;
        g_trans[gp1 + tid]       = a0y + bf0;
        g_trans[gp1 + 256 + tid] = a1y + bf1;
    }
}

// ---------------- persistent scan kernel ----------------
__global__ void __launch_bounds__(256) k_persist(
    const int*   __restrict__ labels,  const float* __restrict__ emb,
    const float* __restrict__ b_ih,    const float* __restrict__ b_hh,
    const float* __restrict__ W_q,     const float* __restrict__ b_q,
    const float* __restrict__ w_alpha, const float* __restrict__ b_alpha,
    const float* __restrict__ cnn,
    const float* __restrict__ W_state, const float* __restrict__ b_state,
    const float* __restrict__ W_emb,   const float* __restrict__ b_emb,
    const float* __restrict__ W_ctx,   const float* __restrict__ b_ctx,
    const float* __restrict__ W_out,   const float* __restrict__ b_out,
    const float* __restrict__ W_init,  const float* __restrict__ b_init,
    const float* __restrict__ locp,    const float* __restrict__ W_loc,
    const float* __restrict__ b_loc,
    float* __restrict__ probs_out, float* __restrict__ alphas_out,
    float* __restrict__ ctxs_out,  float* __restrict__ outs_out){

    int blk = blockIdx.x;
    int tid = threadIdx.x, wid = tid>>5, lane = tid&31;
    unsigned bar = 0;

    __shared__ __align__(16) float s_part[32][256];  // energy partials
    __shared__ __align__(8)  u64   s_nbd[11][42];    // duplicated-pair neighborhood
    __shared__ float s_am[HWN];
    __shared__ float s_vals[304];
    __shared__ float s_ctxc[43];
    __shared__ float s_eng[2][32];
    __shared__ float s_red[8];
    __shared__ float s_bc[2];

    // ---- P1: init-state partials (all 128 blocks) ----
    if (blk < 64){
        int b = blk>>3, sl = blk&7;
        int c0 = sl*86, n = min(CC, c0+86) - c0;
        for (int i=tid;i<n;i+=256) s_vals[i] = g_avg[b*CC + c0 + i];
        __syncthreads();
        float p = 0.f;
        for (int rr=0; rr<n; rr++) p += s_vals[rr]*W_init[(c0+rr)*HIDN + tid];
        __stcg(&g_ipart[(b*8 + sl)*HIDN + tid], p);
    } else {
        int b = (blk-64)>>3, sl = (blk-64)&7;
        int l0 = sl*54;
        for (int i=tid;i<54;i+=256) s_vals[i] = locp[b*LOCN + l0 + i];
        __syncthreads();
        float p = 0.f;
        #pragma unroll 2
        for (int rr=0; rr<54; rr++) p += s_vals[rr]*W_loc[(l0+rr)*HIDN + tid];
        __stcg(&g_lpart[(b*8 + sl)*HIDN + tid], p);
    }
    gsync(bar);

    // ---- P2: combine -> hidden0 (buffer 0), locw (8 blocks) ----
    if (blk < 8){
        int b = blk, j = tid;
        float h0 = b_init[j];
        float lw = b_loc[j];
        #pragma unroll
        for (int p=0;p<8;p++){
            h0 += __ldcg(&g_ipart[(b*8 + p)*HIDN + j]);
            lw += __ldcg(&g_lpart[(b*8 + p)*HIDN + j]);
        }
        __stcg(&g_hidden[b*HIDN + j], ftanh(h0));
        __stcg(&g_locw[b*HIDN + j], lw);
    }
    gsync(bar);

    // ======== scan: 3 gsyncs per step ========
    for (int t = 0; t < TT; t++){
        int hcur = (t & 1) * BB*HIDN;
        int hnxt = ((t+1) & 1) * BB*HIDN;
        __syncthreads();   // protect shared reuse vs trailing D2 of prev step

        // ---- A1: GRU gate partials (all 128 blocks; (b, part16)) ----
        {
            int b = blk >> 4, part = blk & 15;
            int tok = (t == 0) ? 1 : labels[b*TT + t - 1];
            if (tid < 16)       s_vals[tid] = emb[tok*HIDN + part*16 + tid];
            else if (tid < 32)  s_vals[tid] = __ldcg(&g_hidden[hcur + b*HIDN + part*16 + tid - 16]);
            __syncthreads();
            int j = tid;
            float p0=0.f,p1=0.f,p2=0.f,p3=0.f,p4=0.f,p5=0.f;
            #pragma unroll
            for (int ii=0; ii<16; ii++){
                int i = part*16 + ii;
                float e = s_vals[ii], hh = s_vals[16+ii];
                const float* wi = &g_WihT[i*768];
                const float* wh = &g_WhhT[i*768];
                p0 += e*wi[j];      p1 += e*wi[256+j];  p2 += e*wi[512+j];
                p3 += hh*wh[j];     p4 += hh*wh[256+j]; p5 += hh*wh[512+j];
            }
            float* gp = &g_gpart[(b*16 + part)*6*HIDN];
            __stcg(&gp[j], p0);      __stcg(&gp[256+j], p1);  __stcg(&gp[512+j], p2);
            __stcg(&gp[768+j], p3);  __stcg(&gp[1024+j], p4); __stcg(&gp[1280+j], p5);
        }
        gsync(bar);

        // ---- combined B: [A23 on 16 blocks] + conv(all) + flag + epilogue ----
        {
            int b = blk >> 4, h = blk & 15;
            // A23: combine gates + query (blocks 0-15), then raise flag
            if (blk < 16){
                int ab = blk >> 1, half = blk & 1;
                int j = tid;
                int tok = (t == 0) ? 1 : labels[ab*TT + t - 1];
                float a0=b_ih[j], a1=b_ih[256+j], a2=b_ih[512+j];
                float a3=b_hh[j], a4=b_hh[256+j], a5=b_hh[512+j];
                #pragma unroll
                for (int p=0;p<16;p++){
                    const float* gp = &g_gpart[(ab*16 + p)*6*HIDN];
                    a0 += __ldcg(&gp[j]);      a1 += __ldcg(&gp[256+j]);  a2 += __ldcg(&gp[512+j]);
                    a3 += __ldcg(&gp[768+j]);  a4 += __ldcg(&gp[1024+j]); a5 += __ldcg(&gp[1280+j]);
                }
                float r = fsig(a0 + a3);
                float z = fsig(a1 + a4);
                float n = ftanh(a2 + r*a5);
                float hv = __ldcg(&g_hidden[hcur + ab*HIDN + j]);
                float hn = (1.f - z)*n + z*hv;
                if (half == 0){
                    __stcg(&g_hidden[hnxt + ab*HIDN + j], hn);
                    __stcg(&g_et[ab*HIDN + j], emb[tok*HIDN + j]);
                }
                s_vals[j] = hn;
                __syncthreads();
                int j2 = half*256 + tid;
                float q0a=0.f, q1a=0.f, q2a=0.f, q3a=0.f;
                #pragma unroll
                for (int i=0;i<HIDN;i+=4){
                    q0a += s_vals[i  ]*W_q[(i  )*AA + j2];
                    q1a += s_vals[i+1]*W_q[(i+1)*AA + j2];
                    q2a += s_vals[i+2]*W_q[(i+2)*AA + j2];
                    q3a += s_vals[i+3]*W_q[(i+3)*AA + j2];
                }
                __stcg(&g_query[ab*AA + j2], b_q[j2] + ((q0a+q1a)+(q2a+q3a)));
                __threadfence();
                __syncthreads();
                if (tid == 0) atomicAdd(&g_qcnt, 1u);
            }
            // conv + (deferred) epilogue
            float wa0 = w_alpha[tid], wa1 = w_alpha[256 + tid];
            float ba = b_alpha[0];
            float q0 = 0.f, q1 = 0.f;
            for (int tile=0; tile<2; tile++){
                int w0 = tile*32;
                __syncthreads();
                for (int idx=tid; idx<11*42; idx+=256){
                    int r = idx/42, cc = idx%42;
                    int gh = h - 5 + r, gw = w0 - 5 + cc;
                    float v = 0.f;
                    if (gh >= 0 && gh < HH && gw >= 0 && gw < WWD)
                        v = __ldcg(&g_alpha_sum[b*HWN + gh*WWD + gw]);
                    s_nbd[r][cc] = pack2(v, v);
                }
                __syncthreads();
                u64 acc[32];
                #pragma unroll
                for (int i=0;i<32;i++) acc[i]=0ull;
                u64 mpA[11], mpB[11];
                LOAD_MP(mpA, 0);
                #pragma unroll 1
                for (int pyb=0; pyb<5; pyb++){
                    int py0 = 2*pyb;
                    LOAD_MP(mpB, py0+1);
                    CONV_ROW(py0, mpA);
                    LOAD_MP(mpA, py0+2);
                    CONV_ROW(py0+1, mpB);
                }
                CONV_ROW(10, mpA);
                if (tile == 0){
                    // wait until all 16 query halves are published
                    if (tid == 0){
                        unsigned tgt = 16u*(unsigned)(t+1);
                        unsigned v;
                        do {
                            asm volatile("ld.acquire.gpu.u32 %0, [%1];" : "=r"(v) : "l"(&g_qcnt) : "memory");
                        } while (v < tgt);
                    }
                    __syncthreads();
                    q0 = __ldcg(&g_query[b*AA + tid]);
                    q1 = __ldcg(&g_query[b*AA + 256 + tid]);
                }
                size_t gbase = (size_t)((b*HH + h)*WWD + w0)*AA + tid;
                #pragma unroll
                for (int pix=0;pix<32;pix++){
                    float a0, a1;
                    unpack2(acc[pix], a0, a1);
                    float s0 = ftanh(q0 + g_trans[gbase + (size_t)pix*AA]       + a0);
                    float s1 = ftanh(q1 + g_trans[gbase + (size_t)pix*AA + 256] + a1);
                    s_part[pix][tid] = wa0*s0 + wa1*s1;
                }
                __syncthreads();
                #pragma unroll
                for (int k=0;k<4;k++){
                    int pix = wid*4 + k;
                    float s = 0.f;
                    #pragma unroll
                    for (int m=0;m<8;m++) s += s_part[pix][lane + 32*m];
                    s = wred(s);
                    if (lane == 0){
                        __stcg(&g_energy[b*HWN + h*WWD + w0 + pix], s + ba);
                        s_eng[tile][pix] = s + ba;
                    }
                }
            }
            __syncthreads();
            if (tid < 32){
                float v = fmaxf(s_eng[0][tid], s_eng[1][tid]);
                v = wredmax(v);
                if (tid == 0) __stcg(&g_bmax[blk], v);
            }
        }
        gsync(bar);

        // ---- C: softmax + ctx + out_state partials (all 128; (b, chunk16)) ----
        {
            int b = blk >> 4, chunk = blk & 15;
            float mx = (tid < NBLK) ? __ldcg(&g_bmax[tid]) : -1e30f;
            mx = wredmax(mx);
            if (lane == 0) s_red[wid] = mx;
            __syncthreads();
            if (tid == 0){
                float m2 = s_red[0];
                #pragma unroll
                for (int i=1;i<8;i++) m2 = fmaxf(m2, s_red[i]);
                s_bc[0] = m2;
            }
            __syncthreads();
            mx = s_bc[0];
            float e4[4]; float loc = 0.f;
            int base = b*HWN + tid*4;
            float4 ein = __ldcg((const float4*)&g_energy[base]);
            float4 msk = *(const float4*)&g_mask2[base];
            e4[0] = __expf(ein.x - mx)*msk.x;
            e4[1] = __expf(ein.y - mx)*msk.y;
            e4[2] = __expf(ein.z - mx)*msk.z;
            e4[3] = __expf(ein.w - mx)*msk.w;
            loc = e4[0]+e4[1]+e4[2]+e4[3];
            loc = wred(loc);
            __syncthreads();
            if (lane == 0) s_red[wid] = loc;
            __syncthreads();
            if (tid == 0){
                float s = 0.f;
                #pragma unroll
                for (int i=0;i<8;i++) s += s_red[i];
                s_bc[1] = __fdividef(1.f, s + 1e-10f);
            }
            __syncthreads();
            float inv = s_bc[1];
            #pragma unroll
            for (int k=0;k<4;k++){
                float a = e4[k]*inv;
                int hw = tid*4 + k;
                s_am[hw] = (a > 0.02f) ? a : 0.f;
                if (chunk == 0){
                    alphas_out[(size_t)(b*TT + t)*HWN + hw] = a;
                    float as = __ldcg(&g_alpha_sum[b*HWN + hw]) + a;
                    __stcg(&g_alpha_sum[b*HWN + hw], as);
                }
            }
            // stage this part's 32 hidden/et rows (chunks 0-7: hidden, 8-15: e_t)
            if (tid < 32){
                int r = chunk*32 + tid;
                s_vals[tid] = (r < 256) ? __ldcg(&g_hidden[hnxt + b*HIDN + r])
                                        : __ldcg(&g_et[b*HIDN + r - 256]);
            }
            __syncthreads();
            int c0 = chunk*43, cend = min(CC, c0+43);
            for (int c = c0 + wid; c < cend; c += 8){
                const float* p = cnn + (size_t)(b*CC + c)*HWN;
                float s = 0.f;
                #pragma unroll
                for (int m=0;m<8;m++){
                    float4 a4 = *(const float4*)&s_am[lane*4 + 128*m];
                    float4 p4 = *(const float4*)&p[lane*4 + 128*m];
                    s += a4.x*p4.x + a4.y*p4.y + a4.z*p4.z + a4.w*p4.w;
                }
                s = wred(s);
                if (lane == 0){
                    __stcg(&g_ctx[b*CC + c], s);
                    ctxs_out[(size_t)t*BB*CC + b*CC + c] = s;
                    s_ctxc[c - c0] = s;
                }
            }
            __syncthreads();
            // out_state partial: ctx chunk + 32 hidden/et rows -> one opart slot
            int n = cend - c0;
            float s = 0.f;
            for (int cc=0; cc<n; cc++)
                s += s_ctxc[cc]*W_ctx[(c0+cc)*HIDN + tid];
            const float* Wbase = (chunk < 8) ? &W_state[(chunk*32)*HIDN]
                                             : &W_emb[(chunk*32 - 256)*HIDN];
            #pragma unroll 8
            for (int rr=0; rr<32; rr++)
                s += s_vals[rr]*Wbase[rr*HIDN + tid];
            __stcg(&g_opart[(b*16 + chunk)*HIDN + tid], s);
        }
        gsync(bar);

        // ---- D2: maxout + vocab projection (8 blocks); overlaps next A1 ----
        if (blk < 8){
            int b = blk, j = tid;
            float s = b_state[j] + b_emb[j] + b_ctx[j];
            #pragma unroll
            for (int p=0;p<16;p++) s += __ldcg(&g_opart[(b*16 + p)*HIDN + j]);
            s = fmaxf(s, __ldcg(&g_locw[b*HIDN + j]));
            outs_out[(size_t)t*BB*HIDN + b*HIDN + j] = s;
            s_vals[j] = s;
            __syncthreads();
            if (j < VV){
                float p0=0.f, p1=0.f, p2=0.f, p3=0.f;
                #pragma unroll
                for (int i=0;i<HIDN;i+=4){
                    p0 += s_vals[i  ]*W_out[(i  )*VV + j];
                    p1 += s_vals[i+1]*W_out[(i+1)*VV + j];
                    p2 += s_vals[i+2]*W_out[(i+2)*VV + j];
                    p3 += s_vals[i+3]*W_out[(i+3)*VV + j];
                }
                probs_out[(size_t)(b*TT + t)*VV + j] = b_out[j] + ((p0+p1)+(p2+p3));
            }
        }
        // no gsync: next A1 writes only g_gpart, untouched by D2; shared
        // reuse is protected by the __syncthreads at loop top.
    }
}

// ---------------- launch ----------------
extern "C" void kernel_launch(void* const* d_in, const int* in_sizes, int n_in,
                              void* d_out, int out_size){
    const float* cnn     = (const float*)d_in[0];
    const int*   labels  = (const int*  )d_in[1];
    const float* locp    = (const float*)d_in[2];
    const float* imask   = (const float*)d_in[3];
    const float* W_init  = (const float*)d_in[5];
    const float* b_init  = (const float*)d_in[6];
    const float* emb     = (const float*)d_in[7];
    const float* W_ih    = (const float*)d_in[8];
    const float* W_hh    = (const float*)d_in[9];
    const float* b_ih    = (const float*)d_in[10];
    const float* b_hh    = (const float*)d_in[11];
    const float* W_q     = (const float*)d_in[12];
    const float* b_q     = (const float*)d_in[13];
    const float* K_cov   = (const float*)d_in[14];
    const float* W_cov   = (const float*)d_in[15];
    const float* w_alpha = (const float*)d_in[16];
    const float* b_alpha = (const float*)d_in[17];
    const float* K_feat  = (const float*)d_in[18];
    const float* b_feat  = (const float*)d_in[19];
    const float* W_state = (const float*)d_in[20];
    const float* b_state = (const float*)d_in[21];
    const float* W_emb   = (const float*)d_in[22];
    const float* b_emb   = (const float*)d_in[23];
    const float* W_ctx   = (const float*)d_in[24];
    const float* b_ctx   = (const float*)d_in[25];
    const float* W_out   = (const float*)d_in[26];
    const float* b_out   = (const float*)d_in[27];
    const float* W_loc   = (const float*)d_in[28];
    const float* b_loc   = (const float*)d_in[29];

    float* out        = (float*)d_out;
    float* probs_out  = out;                                   // B*T*V
    float* alphas_out = probs_out + (size_t)BB*TT*VV;          // B*T*H*W
    float* ctxs_out   = alphas_out + (size_t)BB*TT*HWN;        // T*B*C
    float* outs_out   = ctxs_out + (size_t)TT*BB*CC;           // T*B*HID

    k_prep<<<1489, 256>>>(W_ih, W_hh, K_feat, K_cov, W_cov);
    k_avgmask<<<dim3(8, BB), 256>>>(imask, cnn);
    k_trans<<<dim3(4, HH, BB), 256>>>(cnn, b_feat);

    k_persist<<<NBLK, 256>>>(labels, emb, b_ih, b_hh, W_q, b_q,
                             w_alpha, b_alpha, cnn,
                             W_state, b_state, W_emb, b_emb,
                             W_ctx, b_ctx, W_out, b_out,
                             W_init, b_init, locp, W_loc, b_loc,
                             probs_out, alphas_out, ctxs_out, outs_out);
    (void)in_sizes; (void)n_in; (void)out_size;
}

// round 15
// speedup vs baseline: 1.8323x; 1.0071x over previous
#include <cuda_runtime.h>

#define BB   8
#define TT   48
#define CC   684
#define HH   16
#define WWD  64
#define HWN  1024
#define HIDN 256
#define AA   512
#define VV   111
#define LOCN 432
#define NBLK 128

typedef unsigned long long u64;

// ---------------- device scratch (static; no allocation) ----------------
__device__ unsigned g_barcnt;
__device__ unsigned g_qcnt;            // query-ready flag (monotonic)
__device__ float g_mask2[BB*HWN];
__device__ float g_avg[BB*CC];
__device__ float g_hidden[2*BB*HIDN];  // double-buffered by step parity
__device__ float g_locw[BB*HIDN];
__device__ float g_query[BB*AA];
__device__ float g_et[BB*HIDN];
__device__ float g_alpha_sum[BB*HWN];
__device__ float g_energy[BB*HWN];
__device__ float g_bmax[NBLK];         // per-block energy max
__device__ float g_ctx[BB*CC];
__device__ float g_gpart[BB*16*6*HIDN];
__device__ float g_opart[BB*16*HIDN];
__device__ float g_ipart[64*HIDN];
__device__ float g_lpart[64*HIDN];
__device__ float2 g_Mp[121*256];       // paired (M[p][a], M[p][a+256])
__device__ float g_KfT[CC*AA];         // K_feat transposed [c][a]
__device__ float g_WihT[HIDN*768];     // [i][gate_j]
__device__ float g_WhhT[HIDN*768];
__device__ float2 g_trans2[(size_t)BB*HWN*256]; // paired (t[a], t[a+256]); 16.7 MB

__device__ __forceinline__ float wred(float v){
    #pragma unroll
    for (int o=16;o;o>>=1) v += __shfl_xor_sync(0xFFFFFFFFu, v, o);
    return v;
}
__device__ __forceinline__ float wredmax(float v){
    #pragma unroll
    for (int o=16;o;o>>=1) v = fmaxf(v, __shfl_xor_sync(0xFFFFFFFFu, v, o));
    return v;
}
__device__ __forceinline__ float ftanh(float x){
    return 1.f - __fdividef(2.f, __expf(2.f*x) + 1.f);
}
__device__ __forceinline__ float fsig(float x){
    return __fdividef(1.f, 1.f + __expf(-x));
}
__device__ __forceinline__ u64 ffma2(u64 a, u64 b, u64 c){
    u64 d;
    asm("fma.rn.f32x2 %0, %1, %2, %3;" : "=l"(d) : "l"(a), "l"(b), "l"(c));
    return d;
}
__device__ __forceinline__ u64 pack2(float x, float y){
    u64 d; asm("mov.b64 %0, {%1, %2};" : "=l"(d) : "f"(x), "f"(y)); return d;
}
__device__ __forceinline__ void unpack2(u64 v, float& x, float& y){
    asm("mov.b64 {%0, %1}, %2;" : "=f"(x), "=f"(y) : "l"(v));
}

// grid-wide barrier (canonical ordering; validated in rounds 5-11)
__device__ __forceinline__ void gsync(unsigned &target){
    __threadfence();
    __syncthreads();
    target += NBLK;
    if (threadIdx.x == 0){
        atomicAdd(&g_barcnt, 1u);
        unsigned v;
        do {
            asm volatile("ld.acquire.gpu.u32 %0, [%1];" : "=r"(v) : "l"(&g_barcnt) : "memory");
        } while (v < target);
    }
    __syncthreads();
}

// phase-B helpers: textual macros keep register arrays register-resident
#define LOAD_MP(mp, py) do { \
    _Pragma("unroll") \
    for (int px=0;px<11;px++){ \
        float2 m2 = g_Mp[((py)*11+px)*256 + tid]; \
        mp[px] = pack2(m2.x, m2.y); \
    } } while(0)

#define CONV_ROW(py, mp) do { \
    _Pragma("unroll") \
    for (int px=0;px<11;px++){ \
        _Pragma("unroll") \
        for (int pix=0;pix<32;pix++) \
            acc[pix] = ffma2(s_nbd[py][px+pix], mp[px], acc[pix]); \
    } } while(0)

// ---------------- setup kernel 1: transposes + fused coverage matrix ----------------
__global__ void k_prep(const float* __restrict__ W_ih,
                       const float* __restrict__ W_hh,
                       const float* __restrict__ K_feat,
                       const float* __restrict__ K_cov,
                       const float* __restrict__ W_cov){
    int bx = blockIdx.x, tid = threadIdx.x;
    if (bx < 1368){
        int i = bx*256 + tid;
        if (i < 768*256){
            int r = i/256, c = i%256;
            g_WihT[c*768 + r] = W_ih[i];
            g_WhhT[c*768 + r] = W_hh[i];
        }
        if (i < 512*684){
            int a = i/684, c = i%684;
            g_KfT[c*512 + a] = K_feat[i];
        }
    } else {
        int p = bx - 1368;   // 0..120
        float s0 = 0.f, s1 = 0.f;
        #pragma unroll 4
        for (int c=0;c<512;c++){
            float k = K_cov[c*121 + p];
            s0 += k * W_cov[c*512 + tid];
            s1 += k * W_cov[c*512 + 256 + tid];
        }
        g_Mp[p*256 + tid] = make_float2(s0, s1);
    }
}

// ---------------- setup kernel 2: mask + avg + zeroing + flag reset ----------------
__global__ void __launch_bounds__(256) k_avgmask(const float* __restrict__ imask,
                                                 const float* __restrict__ cnn){
    int slice = blockIdx.x, b = blockIdx.y;
    int tid = threadIdx.x, wid = tid>>5, lane = tid&31;
    __shared__ float msh[HWN];
    __shared__ float sred[8];
    float s = 0.f;
    #pragma unroll
    for (int k=0;k<4;k++){
        int hw = tid + 256*k;
        int h = hw >> 6, w = hw & 63;
        float v = imask[(size_t)b*262144 + (size_t)(h*16)*1024 + w*16];
        msh[hw] = v; s += v;
        if (slice == 0){
            g_mask2[b*HWN + hw] = v;
            g_alpha_sum[b*HWN + hw] = 0.f;
        }
    }
    if (slice == 0 && b == 0 && tid == 0){ g_barcnt = 0u; g_qcnt = 0u; }
    s = wred(s);
    if (lane == 0) sred[wid] = s;
    __syncthreads();
    float tot = 0.f;
    #pragma unroll
    for (int i=0;i<8;i++) tot += sred[i];
    float inv = __fdividef(1.f, tot);
    int c0 = slice*86, cend = min(CC, c0+86);
    for (int c=c0+wid;c<cend;c+=8){
        const float* p = cnn + (size_t)(b*CC + c)*HWN;
        float acc = 0.f;
        #pragma unroll
        for (int m=0;m<32;m++) acc += msh[lane + 32*m] * p[lane + 32*m];
        acc = wred(acc);
        if (lane == 0) g_avg[b*CC + c] = acc*inv;
    }
}

// ---------------- setup kernel 3: one-time 1x1 conv (paired output) ----------------
__global__ void __launch_bounds__(256) k_trans(const float* __restrict__ cnn,
                                               const float* __restrict__ b_feat){
    int w0 = blockIdx.x*16, h = blockIdx.y, b = blockIdx.z;
    int tid = threadIdx.x;
    __shared__ __align__(16) float X[64][16];
    u64 acc0[8], acc1[8];
    #pragma unroll
    for (int i=0;i<8;i++){ acc0[i]=0ull; acc1[i]=0ull; }
    for (int c0=0;c0<CC;c0+=64){
        int nc = min(64, CC-c0);
        __syncthreads();
        for (int idx=tid; idx<nc*16; idx+=256){
            int cc = idx>>4, pix = idx&15;
            X[cc][pix] = cnn[(size_t)(b*CC + c0+cc)*HWN + h*WWD + w0 + pix];
        }
        __syncthreads();
        for (int cc=0; cc<nc; cc++){
            float k0 = g_KfT[(c0+cc)*AA + tid];
            float k1 = g_KfT[(c0+cc)*AA + 256 + tid];
            u64 k0p = pack2(k0,k0), k1p = pack2(k1,k1);
            #pragma unroll
            for (int k=0;k<8;k++){
                u64 x = *(const u64*)&X[cc][2*k];
                acc0[k] = ffma2(x, k0p, acc0[k]);
                acc1[k] = ffma2(x, k1p, acc1[k]);
            }
        }
    }
    float bf0 = b_feat[tid], bf1 = b_feat[256+tid];
    #pragma unroll
    for (int k=0;k<8;k++){
        float a0x,a0y,a1x,a1y;
        unpack2(acc0[k], a0x, a0y);
        unpack2(acc1[k], a1x, a1y);
        size_t gp0 = (size_t)((b*HH + h)*WWD + w0 + 2*k)*256;
        size_t gp1 = gp0 + 256;
        g_trans2[gp0 + tid] = make_float2(a0x + bf0, a1x + bf1);
        g_trans2[gp1 + tid] = make_float2(a0y + bf0, a1y + bf1);
    }
}

// ---------------- persistent scan kernel (round-11 structure) ----------------
__global__ void __launch_bounds__(256) k_persist(
    const int*   __restrict__ labels,  const float* __restrict__ emb,
    const float* __restrict__ b_ih,    const float* __restrict__ b_hh,
    const float* __restrict__ W_q,     const float* __restrict__ b_q,
    const float* __restrict__ w_alpha, const float* __restrict__ b_alpha,
    const float* __restrict__ cnn,
    const float* __restrict__ W_state, const float* __restrict__ b_state,
    const float* __restrict__ W_emb,   const float* __restrict__ b_emb,
    const float* __restrict__ W_ctx,   const float* __restrict__ b_ctx,
    const float* __restrict__ W_out,   const float* __restrict__ b_out,
    const float* __restrict__ W_init,  const float* __restrict__ b_init,
    const float* __restrict__ locp,    const float* __restrict__ W_loc,
    const float* __restrict__ b_loc,
    float* __restrict__ probs_out, float* __restrict__ alphas_out,
    float* __restrict__ ctxs_out,  float* __restrict__ outs_out){

    int blk = blockIdx.x;
    int tid = threadIdx.x, wid = tid>>5, lane = tid&31;
    unsigned bar = 0;

    __shared__ __align__(16) float s_part[32][256];  // energy partials
    __shared__ __align__(8)  u64   s_nbd[11][42];    // duplicated-pair neighborhood
    __shared__ float s_am[HWN];
    __shared__ float s_vals[304];
    __shared__ float s_ctxc[43];
    __shared__ float s_eng[2][32];
    __shared__ float s_red[8];
    __shared__ float s_bc[2];

    // ---- P1: init-state partials (all 128 blocks) ----
    if (blk < 64){
        int b = blk>>3, sl = blk&7;
        int c0 = sl*86, n = min(CC, c0+86) - c0;
        for (int i=tid;i<n;i+=256) s_vals[i] = g_avg[b*CC + c0 + i];
        __syncthreads();
        float p = 0.f;
        for (int rr=0; rr<n; rr++) p += s_vals[rr]*W_init[(c0+rr)*HIDN + tid];
        __stcg(&g_ipart[(b*8 + sl)*HIDN + tid], p);
    } else {
        int b = (blk-64)>>3, sl = (blk-64)&7;
        int l0 = sl*54;
        for (int i=tid;i<54;i+=256) s_vals[i] = locp[b*LOCN + l0 + i];
        __syncthreads();
        float p = 0.f;
        #pragma unroll 2
        for (int rr=0; rr<54; rr++) p += s_vals[rr]*W_loc[(l0+rr)*HIDN + tid];
        __stcg(&g_lpart[(b*8 + sl)*HIDN + tid], p);
    }
    gsync(bar);

    // ---- P2: combine -> hidden0 (buffer 0), locw (8 blocks) ----
    if (blk < 8){
        int b = blk, j = tid;
        float h0 = b_init[j];
        float lw = b_loc[j];
        #pragma unroll
        for (int p=0;p<8;p++){
            h0 += __ldcg(&g_ipart[(b*8 + p)*HIDN + j]);
            lw += __ldcg(&g_lpart[(b*8 + p)*HIDN + j]);
        }
        __stcg(&g_hidden[b*HIDN + j], ftanh(h0));
        __stcg(&g_locw[b*HIDN + j], lw);
    }
    gsync(bar);

    // ======== scan: 3 gsyncs per step ========
    for (int t = 0; t < TT; t++){
        int hcur = (t & 1) * BB*HIDN;
        int hnxt = ((t+1) & 1) * BB*HIDN;
        __syncthreads();   // protect shared reuse vs trailing D2 of prev step

        // ---- A1: GRU gate partials (all 128 blocks; (b, part16)) ----
        {
            int b = blk >> 4, part = blk & 15;
            int tok = (t == 0) ? 1 : labels[b*TT + t - 1];
            if (tid < 16)       s_vals[tid] = emb[tok*HIDN + part*16 + tid];
            else if (tid < 32)  s_vals[tid] = __ldcg(&g_hidden[hcur + b*HIDN + part*16 + tid - 16]);
            __syncthreads();
            int j = tid;
            float p0=0.f,p1=0.f,p2=0.f,p3=0.f,p4=0.f,p5=0.f;
            #pragma unroll
            for (int ii=0; ii<16; ii++){
                int i = part*16 + ii;
                float e = s_vals[ii], hh = s_vals[16+ii];
                const float* wi = &g_WihT[i*768];
                const float* wh = &g_WhhT[i*768];
                p0 += e*wi[j];      p1 += e*wi[256+j];  p2 += e*wi[512+j];
                p3 += hh*wh[j];     p4 += hh*wh[256+j]; p5 += hh*wh[512+j];
            }
            float* gp = &g_gpart[(b*16 + part)*6*HIDN];
            __stcg(&gp[j], p0);      __stcg(&gp[256+j], p1);  __stcg(&gp[512+j], p2);
            __stcg(&gp[768+j], p3);  __stcg(&gp[1024+j], p4); __stcg(&gp[1280+j], p5);
        }
        gsync(bar);

        // ---- X: [A23 on 16 blocks] + conv(all) + flag + epilogue ----
        {
            int b = blk >> 4, h = blk & 15;
            if (blk < 16){
                int ab = blk >> 1, half = blk & 1;
                int j = tid;
                int tok = (t == 0) ? 1 : labels[ab*TT + t - 1];
                float a0=b_ih[j], a1=b_ih[256+j], a2=b_ih[512+j];
                float a3=b_hh[j], a4=b_hh[256+j], a5=b_hh[512+j];
                #pragma unroll
                for (int p=0;p<16;p++){
                    const float* gp = &g_gpart[(ab*16 + p)*6*HIDN];
                    a0 += __ldcg(&gp[j]);      a1 += __ldcg(&gp[256+j]);  a2 += __ldcg(&gp[512+j]);
                    a3 += __ldcg(&gp[768+j]);  a4 += __ldcg(&gp[1024+j]); a5 += __ldcg(&gp[1280+j]);
                }
                float r = fsig(a0 + a3);
                float z = fsig(a1 + a4);
                float n = ftanh(a2 + r*a5);
                float hv = __ldcg(&g_hidden[hcur + ab*HIDN + j]);
                float hn = (1.f - z)*n + z*hv;
                if (half == 0){
                    __stcg(&g_hidden[hnxt + ab*HIDN + j], hn);
                    __stcg(&g_et[ab*HIDN + j], emb[tok*HIDN + j]);
                }
                s_vals[j] = hn;
                __syncthreads();
                int j2 = half*256 + tid;
                float q0a=0.f, q1a=0.f, q2a=0.f, q3a=0.f;
                #pragma unroll
                for (int i=0;i<HIDN;i+=4){
                    q0a += s_vals[i  ]*W_q[(i  )*AA + j2];
                    q1a += s_vals[i+1]*W_q[(i+1)*AA + j2];
                    q2a += s_vals[i+2]*W_q[(i+2)*AA + j2];
                    q3a += s_vals[i+3]*W_q[(i+3)*AA + j2];
                }
                __stcg(&g_query[ab*AA + j2], b_q[j2] + ((q0a+q1a)+(q2a+q3a)));
                __threadfence();
                __syncthreads();
                if (tid == 0) atomicAdd(&g_qcnt, 1u);
            }
            // conv + (deferred) epilogue
            float wa0 = w_alpha[tid], wa1 = w_alpha[256 + tid];
            float ba = b_alpha[0];
            float q0 = 0.f, q1 = 0.f;
            for (int tile=0; tile<2; tile++){
                int w0 = tile*32;
                __syncthreads();
                for (int idx=tid; idx<11*42; idx+=256){
                    int r = idx/42, cc = idx%42;
                    int gh = h - 5 + r, gw = w0 - 5 + cc;
                    float v = 0.f;
                    if (gh >= 0 && gh < HH && gw >= 0 && gw < WWD)
                        v = __ldcg(&g_alpha_sum[b*HWN + gh*WWD + gw]);
                    s_nbd[r][cc] = pack2(v, v);
                }
                __syncthreads();
                u64 acc[32];
                #pragma unroll
                for (int i=0;i<32;i++) acc[i]=0ull;
                u64 mpA[11], mpB[11];
                LOAD_MP(mpA, 0);
                #pragma unroll 1
                for (int pyb=0; pyb<5; pyb++){
                    int py0 = 2*pyb;
                    LOAD_MP(mpB, py0+1);
                    CONV_ROW(py0, mpA);
                    LOAD_MP(mpA, py0+2);
                    CONV_ROW(py0+1, mpB);
                }
                CONV_ROW(10, mpA);
                if (tile == 0){
                    // wait until all 16 query halves are published
                    if (tid == 0){
                        unsigned tgt = 16u*(unsigned)(t+1);
                        unsigned v;
                        do {
                            asm volatile("ld.acquire.gpu.u32 %0, [%1];" : "=r"(v) : "l"(&g_qcnt) : "memory");
                        } while (v < tgt);
                    }
                    __syncthreads();
                    q0 = __ldcg(&g_query[b*AA + tid]);
                    q1 = __ldcg(&g_query[b*AA + 256 + tid]);
                }
                size_t gbase = (size_t)((b*HH + h)*WWD + w0)*256 + tid;
                #pragma unroll
                for (int pix=0;pix<32;pix++){
                    float a0, a1;
                    unpack2(acc[pix], a0, a1);
                    float2 tv = g_trans2[gbase + (size_t)pix*256];
                    float s0 = ftanh(q0 + tv.x + a0);
                    float s1 = ftanh(q1 + tv.y + a1);
                    s_part[pix][tid] = wa0*s0 + wa1*s1;
                }
                __syncthreads();
                #pragma unroll
                for (int k=0;k<4;k++){
                    int pix = wid*4 + k;
                    float s = 0.f;
                    #pragma unroll
                    for (int m=0;m<8;m++) s += s_part[pix][lane + 32*m];
                    s = wred(s);
                    if (lane == 0){
                        __stcg(&g_energy[b*HWN + h*WWD + w0 + pix], s + ba);
                        s_eng[tile][pix] = s + ba;
                    }
                }
            }
            __syncthreads();
            if (tid < 32){
                float v = fmaxf(s_eng[0][tid], s_eng[1][tid]);
                v = wredmax(v);
                if (tid == 0) __stcg(&g_bmax[blk], v);
            }
        }
        gsync(bar);

        // ---- C: softmax + ctx + out_state partials (all 128; (b, chunk16)) ----
        {
            int b = blk >> 4, chunk = blk & 15;
            float mx = (tid < NBLK) ? __ldcg(&g_bmax[tid]) : -1e30f;
            mx = wredmax(mx);
            if (lane == 0) s_red[wid] = mx;
            __syncthreads();
            if (tid == 0){
                float m2 = s_red[0];
                #pragma unroll
                for (int i=1;i<8;i++) m2 = fmaxf(m2, s_red[i]);
                s_bc[0] = m2;
            }
            __syncthreads();
            mx = s_bc[0];
            float e4[4]; float loc = 0.f;
            int base = b*HWN + tid*4;
            float4 ein = __ldcg((const float4*)&g_energy[base]);
            float4 msk = *(const float4*)&g_mask2[base];
            e4[0] = __expf(ein.x - mx)*msk.x;
            e4[1] = __expf(ein.y - mx)*msk.y;
            e4[2] = __expf(ein.z - mx)*msk.z;
            e4[3] = __expf(ein.w - mx)*msk.w;
            loc = e4[0]+e4[1]+e4[2]+e4[3];
            loc = wred(loc);
            __syncthreads();
            if (lane == 0) s_red[wid] = loc;
            __syncthreads();
            if (tid == 0){
                float s = 0.f;
                #pragma unroll
                for (int i=0;i<8;i++) s += s_red[i];
                s_bc[1] = __fdividef(1.f, s + 1e-10f);
            }
            __syncthreads();
            float inv = s_bc[1];
            #pragma unroll
            for (int k=0;k<4;k++){
                float a = e4[k]*inv;
                int hw = tid*4 + k;
                s_am[hw] = (a > 0.02f) ? a : 0.f;
                if (chunk == 0){
                    alphas_out[(size_t)(b*TT + t)*HWN + hw] = a;
                    float as = __ldcg(&g_alpha_sum[b*HWN + hw]) + a;
                    __stcg(&g_alpha_sum[b*HWN + hw], as);
                }
            }
            // stage this part's 32 hidden/et rows (chunks 0-7: hidden, 8-15: e_t)
            if (tid < 32){
                int r = chunk*32 + tid;
                s_vals[tid] = (r < 256) ? __ldcg(&g_hidden[hnxt + b*HIDN + r])
                                        : __ldcg(&g_et[b*HIDN + r - 256]);
            }
            __syncthreads();
            int c0 = chunk*43, cend = min(CC, c0+43);
            for (int c = c0 + wid; c < cend; c += 8){
                const float* p = cnn + (size_t)(b*CC + c)*HWN;
                float s = 0.f;
                #pragma unroll
                for (int m=0;m<8;m++){
                    float4 a4 = *(const float4*)&s_am[lane*4 + 128*m];
                    float4 p4 = *(const float4*)&p[lane*4 + 128*m];
                    s += a4.x*p4.x + a4.y*p4.y + a4.z*p4.z + a4.w*p4.w;
                }
                s = wred(s);
                if (lane == 0){
                    __stcg(&g_ctx[b*CC + c], s);
                    ctxs_out[(size_t)t*BB*CC + b*CC + c] = s;
                    s_ctxc[c - c0] = s;
                }
            }
            __syncthreads();
            // out_state partial: ctx chunk + 32 hidden/et rows -> one opart slot
            {
                int n = cend - c0;
                float s = 0.f;
                for (int cc=0; cc<n; cc++)
                    s += s_ctxc[cc]*W_ctx[(c0+cc)*HIDN + tid];
                const float* Wbase = (chunk < 8) ? &W_state[(chunk*32)*HIDN]
                                                 : &W_emb[(chunk*32 - 256)*HIDN];
                #pragma unroll 8
                for (int rr=0; rr<32; rr++)
                    s += s_vals[rr]*Wbase[rr*HIDN + tid];
                __stcg(&g_opart[(b*16 + chunk)*HIDN + tid], s);
            }
        }
        gsync(bar);

        // ---- D2: maxout + vocab projection (8 blocks); overlaps next A1 ----
        if (blk < 8){
            int b = blk, j = tid;
            float s = b_state[j] + b_emb[j] + b_ctx[j];
            #pragma unroll
            for (int p=0;p<16;p++) s += __ldcg(&g_opart[(b*16 + p)*HIDN + j]);
            s = fmaxf(s, __ldcg(&g_locw[b*HIDN + j]));
            outs_out[(size_t)t*BB*HIDN + b*HIDN + j] = s;
            s_vals[j] = s;
            __syncthreads();
            if (j < VV){
                float p0=0.f, p1=0.f, p2=0.f, p3=0.f;
                #pragma unroll
                for (int i=0;i<HIDN;i+=4){
                    p0 += s_vals[i  ]*W_out[(i  )*VV + j];
                    p1 += s_vals[i+1]*W_out[(i+1)*VV + j];
                    p2 += s_vals[i+2]*W_out[(i+2)*VV + j];
                    p3 += s_vals[i+3]*W_out[(i+3)*VV + j];
                }
                probs_out[(size_t)(b*TT + t)*VV + j] = b_out[j] + ((p0+p1)+(p2+p3));
            }
        }
        // no gsync: next A1 writes only g_gpart, untouched by D2; shared
        // reuse is protected by the __syncthreads at loop top.
    }
}

// ---------------- launch ----------------
extern "C" void kernel_launch(void* const* d_in, const int* in_sizes, int n_in,
                              void* d_out, int out_size){
    const float* cnn     = (const float*)d_in[0];
    const int*   labels  = (const int*  )d_in[1];
    const float* locp    = (const float*)d_in[2];
    const float* imask   = (const float*)d_in[3];
    const float* W_init  = (const float*)d_in[5];
    const float* b_init  = (const float*)d_in[6];
    const float* emb     = (const float*)d_in[7];
    const float* W_ih    = (const float*)d_in[8];
    const float* W_hh    = (const float*)d_in[9];
    const float* b_ih    = (const float*)d_in[10];
    const float* b_hh    = (const float*)d_in[11];
    const float* W_q     = (const float*)d_in[12];
    const float* b_q     = (const float*)d_in[13];
    const float* K_cov   = (const float*)d_in[14];
    const float* W_cov   = (const float*)d_in[15];
    const float* w_alpha = (const float*)d_in[16];
    const float* b_alpha = (const float*)d_in[17];
    const float* K_feat  = (const float*)d_in[18];
    const float* b_feat  = (const float*)d_in[19];
    const float* W_state = (const float*)d_in[20];
    const float* b_state = (const float*)d_in[21];
    const float* W_emb   = (const float*)d_in[22];
    const float* b_emb   = (const float*)d_in[23];
    const float* W_ctx   = (const float*)d_in[24];
    const float* b_ctx   = (const float*)d_in[25];
    const float* W_out   = (const float*)d_in[26];
    const float* b_out   = (const float*)d_in[27];
    const float* W_loc   = (const float*)d_in[28];
    const float* b_loc   = (const float*)d_in[29];

    float* out        = (float*)d_out;
    float* probs_out  = out;                                   // B*T*V
    float* alphas_out = probs_out + (size_t)BB*TT*VV;          // B*T*H*W
    float* ctxs_out   = alphas_out + (size_t)BB*TT*HWN;        // T*B*C
    float* outs_out   = ctxs_out + (size_t)TT*BB*CC;           // T*B*HID

    k_prep<<<1489, 256>>>(W_ih, W_hh, K_feat, K_cov, W_cov);
    k_avgmask<<<dim3(8, BB), 256>>>(imask, cnn);
    k_trans<<<dim3(4, HH, BB), 256>>>(cnn, b_feat);

    k_persist<<<NBLK, 256>>>(labels, emb, b_ih, b_hh, W_q, b_q,
                             w_alpha, b_alpha, cnn,
                             W_state, b_state, W_emb, b_emb,
                             W_ctx, b_ctx, W_out, b_out,
                             W_init, b_init, locp, W_loc, b_loc,
                             probs_out, alphas_out, ctxs_out, outs_out);
    (void)in_sizes; (void)n_in; (void)out_size;
}

// round 16
// speedup vs baseline: 1.9114x; 1.0431x over previous
#include <cuda_runtime.h>

#define BB   8
#define TT   48
#define CC   684
#define HH   16
#define WWD  64
#define HWN  1024
#define HIDN 256
#define AA   512
#define VV   111
#define LOCN 432
#define NBLK 128

typedef unsigned long long u64;

// ---------------- device scratch (static; no allocation) ----------------
__device__ unsigned g_barcnt;
__device__ unsigned g_qcnt;            // query-ready flag (monotonic)
__device__ float g_mask2[BB*HWN];
__device__ float g_avg[BB*CC];
__device__ float g_hidden[2*BB*HIDN];  // double-buffered by step parity
__device__ float g_locw[BB*HIDN];
__device__ float g_query[BB*AA];
__device__ float g_et[BB*HIDN];
__device__ float g_alpha_sum[BB*HWN];
__device__ float g_energy[BB*HWN];
__device__ float g_bmax[NBLK];         // per-block energy max
__device__ float g_ctx[BB*CC];
__device__ float g_gpart[BB*16*6*HIDN];
__device__ float g_opart[BB*16*HIDN];
__device__ float g_ipart[64*HIDN];
__device__ float g_lpart[64*HIDN];
__device__ float2 g_Mp[121*256];       // paired (M[p][a], M[p][a+256])
__device__ float g_KfT[CC*AA];         // K_feat transposed [c][a]
__device__ float g_WihT[HIDN*768];     // [i][gate_j]
__device__ float g_WhhT[HIDN*768];
__device__ float2 g_trans2[(size_t)BB*HWN*256]; // paired (t[a], t[a+256]); 16.7 MB

__device__ __forceinline__ float wred(float v){
    #pragma unroll
    for (int o=16;o;o>>=1) v += __shfl_xor_sync(0xFFFFFFFFu, v, o);
    return v;
}
__device__ __forceinline__ float wredmax(float v){
    #pragma unroll
    for (int o=16;o;o>>=1) v = fmaxf(v, __shfl_xor_sync(0xFFFFFFFFu, v, o));
    return v;
}
__device__ __forceinline__ float ftanh(float x){
    return 1.f - __fdividef(2.f, __expf(2.f*x) + 1.f);
}
__device__ __forceinline__ float fsig(float x){
    return __fdividef(1.f, 1.f + __expf(-x));
}
__device__ __forceinline__ u64 ffma2(u64 a, u64 b, u64 c){
    u64 d;
    asm("fma.rn.f32x2 %0, %1, %2, %3;" : "=l"(d) : "l"(a), "l"(b), "l"(c));
    return d;
}
__device__ __forceinline__ u64 pack2(float x, float y){
    u64 d; asm("mov.b64 %0, {%1, %2};" : "=l"(d) : "f"(x), "f"(y)); return d;
}
__device__ __forceinline__ void unpack2(u64 v, float& x, float& y){
    asm("mov.b64 {%0, %1}, %2;" : "=f"(x), "=f"(y) : "l"(v));
}

// grid-wide barrier (canonical ordering; validated in rounds 5-15)
__device__ __forceinline__ void gsync(unsigned &target){
    __threadfence();
    __syncthreads();
    target += NBLK;
    if (threadIdx.x == 0){
        atomicAdd(&g_barcnt, 1u);
        unsigned v;
        do {
            asm volatile("ld.acquire.gpu.u32 %0, [%1];" : "=r"(v) : "l"(&g_barcnt) : "memory");
        } while (v < target);
    }
    __syncthreads();
}

// phase-B helpers: textual macros keep register arrays register-resident
#define LOAD_MP(mp, py) do { \
    _Pragma("unroll") \
    for (int px=0;px<11;px++){ \
        float2 m2 = g_Mp[((py)*11+px)*256 + tid]; \
        mp[px] = pack2(m2.x, m2.y); \
    } } while(0)

#define CONV_ROW(py, mp) do { \
    _Pragma("unroll") \
    for (int px=0;px<11;px++){ \
        _Pragma("unroll") \
        for (int pix=0;pix<32;pix++) \
            acc[pix] = ffma2(s_nbd[py][px+pix], mp[px], acc[pix]); \
    } } while(0)

// ---------------- setup kernel 1: transposes + fused coverage matrix ----------------
__global__ void k_prep(const float* __restrict__ W_ih,
                       const float* __restrict__ W_hh,
                       const float* __restrict__ K_feat,
                       const float* __restrict__ K_cov,
                       const float* __restrict__ W_cov){
    int bx = blockIdx.x, tid = threadIdx.x;
    if (bx < 1368){
        int i = bx*256 + tid;
        if (i < 768*256){
            int r = i/256, c = i%256;
            g_WihT[c*768 + r] = W_ih[i];
            g_WhhT[c*768 + r] = W_hh[i];
        }
        if (i < 512*684){
            int a = i/684, c = i%684;
            g_KfT[c*512 + a] = K_feat[i];
        }
    } else {
        int p = bx - 1368;   // 0..120
        float s0 = 0.f, s1 = 0.f;
        #pragma unroll 4
        for (int c=0;c<512;c++){
            float k = K_cov[c*121 + p];
            s0 += k * W_cov[c*512 + tid];
            s1 += k * W_cov[c*512 + 256 + tid];
        }
        g_Mp[p*256 + tid] = make_float2(s0, s1);
    }
}

// ---------------- setup kernel 2: mask + avg + zeroing + flag reset ----------------
__global__ void __launch_bounds__(256) k_avgmask(const float* __restrict__ imask,
                                                 const float* __restrict__ cnn){
    int slice = blockIdx.x, b = blockIdx.y;
    int tid = threadIdx.x, wid = tid>>5, lane = tid&31;
    __shared__ float msh[HWN];
    __shared__ float sred[8];
    float s = 0.f;
    #pragma unroll
    for (int k=0;k<4;k++){
        int hw = tid + 256*k;
        int h = hw >> 6, w = hw & 63;
        float v = imask[(size_t)b*262144 + (size_t)(h*16)*1024 + w*16];
        msh[hw] = v; s += v;
        if (slice == 0){
            g_mask2[b*HWN + hw] = v;
            g_alpha_sum[b*HWN + hw] = 0.f;
        }
    }
    if (slice == 0 && b == 0 && tid == 0){ g_barcnt = 0u; g_qcnt = 0u; }
    s = wred(s);
    if (lane == 0) sred[wid] = s;
    __syncthreads();
    float tot = 0.f;
    #pragma unroll
    for (int i=0;i<8;i++) tot += sred[i];
    float inv = __fdividef(1.f, tot);
    int c0 = slice*86, cend = min(CC, c0+86);
    for (int c=c0+wid;c<cend;c+=8){
        const float* p = cnn + (size_t)(b*CC + c)*HWN;
        float acc = 0.f;
        #pragma unroll
        for (int m=0;m<32;m++) acc += msh[lane + 32*m] * p[lane + 32*m];
        acc = wred(acc);
        if (lane == 0) g_avg[b*CC + c] = acc*inv;
    }
}

// ---------------- setup kernel 3: one-time 1x1 conv (paired output) ----------------
__global__ void __launch_bounds__(256) k_trans(const float* __restrict__ cnn,
                                               const float* __restrict__ b_feat){
    int w0 = blockIdx.x*16, h = blockIdx.y, b = blockIdx.z;
    int tid = threadIdx.x;
    __shared__ __align__(16) float X[64][16];
    u64 acc0[8], acc1[8];
    #pragma unroll
    for (int i=0;i<8;i++){ acc0[i]=0ull; acc1[i]=0ull; }
    for (int c0=0;c0<CC;c0+=64){
        int nc = min(64, CC-c0);
        __syncthreads();
        for (int idx=tid; idx<nc*16; idx+=256){
            int cc = idx>>4, pix = idx&15;
            X[cc][pix] = cnn[(size_t)(b*CC + c0+cc)*HWN + h*WWD + w0 + pix];
        }
        __syncthreads();
        for (int cc=0; cc<nc; cc++){
            float k0 = g_KfT[(c0+cc)*AA + tid];
            float k1 = g_KfT[(c0+cc)*AA + 256 + tid];
            u64 k0p = pack2(k0,k0), k1p = pack2(k1,k1);
            #pragma unroll
            for (int k=0;k<8;k++){
                u64 x = *(const u64*)&X[cc][2*k];
                acc0[k] = ffma2(x, k0p, acc0[k]);
                acc1[k] = ffma2(x, k1p, acc1[k]);
            }
        }
    }
    float bf0 = b_feat[tid], bf1 = b_feat[256+tid];
    #pragma unroll
    for (int k=0;k<8;k++){
        float a0x,a0y,a1x,a1y;
        unpack2(acc0[k], a0x, a0y);
        unpack2(acc1[k], a1x, a1y);
        size_t gp0 = (size_t)((b*HH + h)*WWD + w0 + 2*k)*256;
        size_t gp1 = gp0 + 256;
        g_trans2[gp0 + tid] = make_float2(a0x + bf0, a1x + bf1);
        g_trans2[gp1 + tid] = make_float2(a0y + bf0, a1y + bf1);
    }
}

// ---------------- persistent scan kernel (2 gsyncs/step; A1 fused into C) ----------------
__global__ void __launch_bounds__(256) k_persist(
    const int*   __restrict__ labels,  const float* __restrict__ emb,
    const float* __restrict__ b_ih,    const float* __restrict__ b_hh,
    const float* __restrict__ W_q,     const float* __restrict__ b_q,
    const float* __restrict__ w_alpha, const float* __restrict__ b_alpha,
    const float* __restrict__ cnn,
    const float* __restrict__ W_state, const float* __restrict__ b_state,
    const float* __restrict__ W_emb,   const float* __restrict__ b_emb,
    const float* __restrict__ W_ctx,   const float* __restrict__ b_ctx,
    const float* __restrict__ W_out,   const float* __restrict__ b_out,
    const float* __restrict__ W_init,  const float* __restrict__ b_init,
    const float* __restrict__ locp,    const float* __restrict__ W_loc,
    const float* __restrict__ b_loc,
    float* __restrict__ probs_out, float* __restrict__ alphas_out,
    float* __restrict__ ctxs_out,  float* __restrict__ outs_out){

    int blk = blockIdx.x;
    int tid = threadIdx.x, wid = tid>>5, lane = tid&31;
    unsigned bar = 0;

    __shared__ __align__(16) float s_part[32][256];  // energy partials
    __shared__ __align__(8)  u64   s_nbd[11][42];    // duplicated-pair neighborhood
    __shared__ float s_am[HWN];
    __shared__ float s_vals[304];
    __shared__ float s_a1[32];
    __shared__ float s_ctxc[43];
    __shared__ float s_eng[2][32];
    __shared__ float s_red[8];
    __shared__ float s_bc[2];

    // ---- P1: init-state partials (all 128 blocks) ----
    if (blk < 64){
        int b = blk>>3, sl = blk&7;
        int c0 = sl*86, n = min(CC, c0+86) - c0;
        for (int i=tid;i<n;i+=256) s_vals[i] = g_avg[b*CC + c0 + i];
        __syncthreads();
        float p = 0.f;
        for (int rr=0; rr<n; rr++) p += s_vals[rr]*W_init[(c0+rr)*HIDN + tid];
        __stcg(&g_ipart[(b*8 + sl)*HIDN + tid], p);
    } else {
        int b = (blk-64)>>3, sl = (blk-64)&7;
        int l0 = sl*54;
        for (int i=tid;i<54;i+=256) s_vals[i] = locp[b*LOCN + l0 + i];
        __syncthreads();
        float p = 0.f;
        #pragma unroll 2
        for (int rr=0; rr<54; rr++) p += s_vals[rr]*W_loc[(l0+rr)*HIDN + tid];
        __stcg(&g_lpart[(b*8 + sl)*HIDN + tid], p);
    }
    gsync(bar);

    // ---- P2: combine -> hidden0 (buffer 0), locw (8 blocks) ----
    if (blk < 8){
        int b = blk, j = tid;
        float h0 = b_init[j];
        float lw = b_loc[j];
        #pragma unroll
        for (int p=0;p<8;p++){
            h0 += __ldcg(&g_ipart[(b*8 + p)*HIDN + j]);
            lw += __ldcg(&g_lpart[(b*8 + p)*HIDN + j]);
        }
        __stcg(&g_hidden[b*HIDN + j], ftanh(h0));
        __stcg(&g_locw[b*HIDN + j], lw);
    }
    gsync(bar);

    // ---- P3: A1 partials for step 0 (all 128 blocks; (b, part16)) ----
    {
        int b = blk >> 4, part = blk & 15;
        if (tid < 16)       s_vals[tid] = emb[1*HIDN + part*16 + tid];   // tok(0)=1
        else if (tid < 32)  s_vals[tid] = __ldcg(&g_hidden[b*HIDN + part*16 + tid - 16]);
        __syncthreads();
        int j = tid;
        float p0=0.f,p1=0.f,p2=0.f,p3=0.f,p4=0.f,p5=0.f;
        #pragma unroll
        for (int ii=0; ii<16; ii++){
            int i = part*16 + ii;
            float e = s_vals[ii], hh = s_vals[16+ii];
            const float* wi = &g_WihT[i*768];
            const float* wh = &g_WhhT[i*768];
            p0 += e*wi[j];      p1 += e*wi[256+j];  p2 += e*wi[512+j];
            p3 += hh*wh[j];     p4 += hh*wh[256+j]; p5 += hh*wh[512+j];
        }
        float* gp = &g_gpart[(b*16 + part)*6*HIDN];
        __stcg(&gp[j], p0);      __stcg(&gp[256+j], p1);  __stcg(&gp[512+j], p2);
        __stcg(&gp[768+j], p3);  __stcg(&gp[1024+j], p4); __stcg(&gp[1280+j], p5);
    }
    gsync(bar);

    // ======== scan: 2 gsyncs per step ========
    for (int t = 0; t < TT; t++){
        int hcur = (t & 1) * BB*HIDN;
        int hnxt = ((t+1) & 1) * BB*HIDN;
        __syncthreads();   // seal shared reuse vs trailing D2 of prev step

        // ---- X: [A23 on 16 blocks] + conv(all) + flag + epilogue ----
        {
            int b = blk >> 4, h = blk & 15;
            if (blk < 16){
                int ab = blk >> 1, half = blk & 1;
                int j = tid;
                int tok = (t == 0) ? 1 : labels[ab*TT + t - 1];
                float a0=b_ih[j], a1=b_ih[256+j], a2=b_ih[512+j];
                float a3=b_hh[j], a4=b_hh[256+j], a5=b_hh[512+j];
                #pragma unroll
                for (int p=0;p<16;p++){
                    const float* gp = &g_gpart[(ab*16 + p)*6*HIDN];
                    a0 += __ldcg(&gp[j]);      a1 += __ldcg(&gp[256+j]);  a2 += __ldcg(&gp[512+j]);
                    a3 += __ldcg(&gp[768+j]);  a4 += __ldcg(&gp[1024+j]); a5 += __ldcg(&gp[1280+j]);
                }
                float r = fsig(a0 + a3);
                float z = fsig(a1 + a4);
                float n = ftanh(a2 + r*a5);
                float hv = __ldcg(&g_hidden[hcur + ab*HIDN + j]);
                float hn = (1.f - z)*n + z*hv;
                if (half == 0){
                    __stcg(&g_hidden[hnxt + ab*HIDN + j], hn);
                    __stcg(&g_et[ab*HIDN + j], emb[tok*HIDN + j]);
                }
                s_vals[j] = hn;
                __syncthreads();
                int j2 = half*256 + tid;
                float q0a=0.f, q1a=0.f, q2a=0.f, q3a=0.f;
                #pragma unroll
                for (int i=0;i<HIDN;i+=4){
                    q0a += s_vals[i  ]*W_q[(i  )*AA + j2];
                    q1a += s_vals[i+1]*W_q[(i+1)*AA + j2];
                    q2a += s_vals[i+2]*W_q[(i+2)*AA + j2];
                    q3a += s_vals[i+3]*W_q[(i+3)*AA + j2];
                }
                __stcg(&g_query[ab*AA + j2], b_q[j2] + ((q0a+q1a)+(q2a+q3a)));
                __threadfence();
                __syncthreads();
                if (tid == 0) atomicAdd(&g_qcnt, 1u);
            }
            // conv + (deferred) epilogue
            float wa0 = w_alpha[tid], wa1 = w_alpha[256 + tid];
            float ba = b_alpha[0];
            float q0 = 0.f, q1 = 0.f;
            for (int tile=0; tile<2; tile++){
                int w0 = tile*32;
                __syncthreads();
                for (int idx=tid; idx<11*42; idx+=256){
                    int r = idx/42, cc = idx%42;
                    int gh = h - 5 + r, gw = w0 - 5 + cc;
                    float v = 0.f;
                    if (gh >= 0 && gh < HH && gw >= 0 && gw < WWD)
                        v = __ldcg(&g_alpha_sum[b*HWN + gh*WWD + gw]);
                    s_nbd[r][cc] = pack2(v, v);
                }
                __syncthreads();
                u64 acc[32];
                #pragma unroll
                for (int i=0;i<32;i++) acc[i]=0ull;
                u64 mpA[11], mpB[11];
                LOAD_MP(mpA, 0);
                #pragma unroll 1
                for (int pyb=0; pyb<5; pyb++){
                    int py0 = 2*pyb;
                    LOAD_MP(mpB, py0+1);
                    CONV_ROW(py0, mpA);
                    LOAD_MP(mpA, py0+2);
                    CONV_ROW(py0+1, mpB);
                }
                CONV_ROW(10, mpA);
                if (tile == 0){
                    if (tid == 0){
                        unsigned tgt = 16u*(unsigned)(t+1);
                        unsigned v;
                        do {
                            asm volatile("ld.acquire.gpu.u32 %0, [%1];" : "=r"(v) : "l"(&g_qcnt) : "memory");
                        } while (v < tgt);
                    }
                    __syncthreads();
                    q0 = __ldcg(&g_query[b*AA + tid]);
                    q1 = __ldcg(&g_query[b*AA + 256 + tid]);
                }
                size_t gbase = (size_t)((b*HH + h)*WWD + w0)*256 + tid;
                #pragma unroll
                for (int pix=0;pix<32;pix++){
                    float a0, a1;
                    unpack2(acc[pix], a0, a1);
                    float2 tv = g_trans2[gbase + (size_t)pix*256];
                    float s0 = ftanh(q0 + tv.x + a0);
                    float s1 = ftanh(q1 + tv.y + a1);
                    s_part[pix][tid] = wa0*s0 + wa1*s1;
                }
                __syncthreads();
                #pragma unroll
                for (int k=0;k<4;k++){
                    int pix = wid*4 + k;
                    float s = 0.f;
                    #pragma unroll
                    for (int m=0;m<8;m++) s += s_part[pix][lane + 32*m];
                    s = wred(s);
                    if (lane == 0){
                        __stcg(&g_energy[b*HWN + h*WWD + w0 + pix], s + ba);
                        s_eng[tile][pix] = s + ba;
                    }
                }
            }
            __syncthreads();
            if (tid < 32){
                float v = fmaxf(s_eng[0][tid], s_eng[1][tid]);
                v = wredmax(v);
                if (tid == 0) __stcg(&g_bmax[blk], v);
            }
        }
        gsync(bar);

        // ---- C: softmax + ctx + opart + A1(t+1) partials (all 128 blocks) ----
        {
            int b = blk >> 4, chunk = blk & 15;
            // stage A1(t+1) inputs (tok for step t+1 is labels[.., t])
            if (t + 1 < TT){
                int tok1 = labels[b*TT + t];
                if (tid < 16)      s_a1[tid] = emb[tok1*HIDN + chunk*16 + tid];
                else if (tid < 32) s_a1[tid] = __ldcg(&g_hidden[hnxt + b*HIDN + chunk*16 + tid - 16]);
            }
            __syncthreads();   // seal s_a1 staging before reductions
            float mx = (tid < NBLK) ? __ldcg(&g_bmax[tid]) : -1e30f;
            mx = wredmax(mx);
            if (lane == 0) s_red[wid] = mx;
            __syncthreads();
            if (tid == 0){
                float m2 = s_red[0];
                #pragma unroll
                for (int i=1;i<8;i++) m2 = fmaxf(m2, s_red[i]);
                s_bc[0] = m2;
            }
            __syncthreads();
            mx = s_bc[0];
            float e4[4]; float loc = 0.f;
            int base = b*HWN + tid*4;
            float4 ein = __ldcg((const float4*)&g_energy[base]);
            float4 msk = *(const float4*)&g_mask2[base];
            e4[0] = __expf(ein.x - mx)*msk.x;
            e4[1] = __expf(ein.y - mx)*msk.y;
            e4[2] = __expf(ein.z - mx)*msk.z;
            e4[3] = __expf(ein.w - mx)*msk.w;
            loc = e4[0]+e4[1]+e4[2]+e4[3];
            loc = wred(loc);
            __syncthreads();
            if (lane == 0) s_red[wid] = loc;
            __syncthreads();
            if (tid == 0){
                float s = 0.f;
                #pragma unroll
                for (int i=0;i<8;i++) s += s_red[i];
                s_bc[1] = __fdividef(1.f, s + 1e-10f);
            }
            __syncthreads();
            float inv = s_bc[1];
            #pragma unroll
            for (int k=0;k<4;k++){
                float a = e4[k]*inv;
                int hw = tid*4 + k;
                s_am[hw] = (a > 0.02f) ? a : 0.f;
                if (chunk == 0){
                    alphas_out[(size_t)(b*TT + t)*HWN + hw] = a;
                    float as = __ldcg(&g_alpha_sum[b*HWN + hw]) + a;
                    __stcg(&g_alpha_sum[b*HWN + hw], as);
                }
            }
            // stage this part's 32 hidden/et rows (chunks 0-7: hidden, 8-15: e_t)
            if (tid < 32){
                int r = chunk*32 + tid;
                s_vals[tid] = (r < 256) ? __ldcg(&g_hidden[hnxt + b*HIDN + r])
                                        : __ldcg(&g_et[b*HIDN + r - 256]);
            }
            __syncthreads();
            int c0 = chunk*43, cend = min(CC, c0+43);
            for (int c = c0 + wid; c < cend; c += 8){
                const float* p = cnn + (size_t)(b*CC + c)*HWN;
                float s = 0.f;
                #pragma unroll
                for (int m=0;m<8;m++){
                    float4 a4 = *(const float4*)&s_am[lane*4 + 128*m];
                    float4 p4 = *(const float4*)&p[lane*4 + 128*m];
                    s += a4.x*p4.x + a4.y*p4.y + a4.z*p4.z + a4.w*p4.w;
                }
                s = wred(s);
                if (lane == 0){
                    __stcg(&g_ctx[b*CC + c], s);
                    ctxs_out[(size_t)t*BB*CC + b*CC + c] = s;
                    s_ctxc[c - c0] = s;
                }
            }
            __syncthreads();
            // out_state partial: ctx chunk + 32 hidden/et rows -> one opart slot
            {
                int n = cend - c0;
                float s = 0.f;
                for (int cc=0; cc<n; cc++)
                    s += s_ctxc[cc]*W_ctx[(c0+cc)*HIDN + tid];
                const float* Wbase = (chunk < 8) ? &W_state[(chunk*32)*HIDN]
                                                 : &W_emb[(chunk*32 - 256)*HIDN];
                #pragma unroll 8
                for (int rr=0; rr<32; rr++)
                    s += s_vals[rr]*Wbase[rr*HIDN + tid];
                __stcg(&g_opart[(b*16 + chunk)*HIDN + tid], s);
            }
            // A1(t+1) partials: 16 rows (chunk*16 .. chunk*16+15)
            if (t + 1 < TT){
                int j = tid;
                float p0=0.f,p1=0.f,p2=0.f,p3=0.f,p4=0.f,p5=0.f;
                #pragma unroll
                for (int ii=0; ii<16; ii++){
                    int i = chunk*16 + ii;
                    float e = s_a1[ii], hh = s_a1[16+ii];
                    const float* wi = &g_WihT[i*768];
                    const float* wh = &g_WhhT[i*768];
                    p0 += e*wi[j];      p1 += e*wi[256+j];  p2 += e*wi[512+j];
                    p3 += hh*wh[j];     p4 += hh*wh[256+j]; p5 += hh*wh[512+j];
                }
                float* gp = &g_gpart[(b*16 + chunk)*6*HIDN];
                __stcg(&gp[j], p0);      __stcg(&gp[256+j], p1);  __stcg(&gp[512+j], p2);
                __stcg(&gp[768+j], p3);  __stcg(&gp[1024+j], p4); __stcg(&gp[1280+j], p5);
            }
        }
        gsync(bar);

        // ---- D2: maxout + vocab projection (8 blocks); overlaps next X ----
        if (blk < 8){
            int b = blk, j = tid;
            float s = b_state[j] + b_emb[j] + b_ctx[j];
            #pragma unroll
            for (int p=0;p<16;p++) s += __ldcg(&g_opart[(b*16 + p)*HIDN + j]);
            s = fmaxf(s, __ldcg(&g_locw[b*HIDN + j]));
            outs_out[(size_t)t*BB*HIDN + b*HIDN + j] = s;
            s_vals[j] = s;
            __syncthreads();
            if (j < VV){
                float p0=0.f, p1=0.f, p2=0.f, p3=0.f;
                #pragma unroll
                for (int i=0;i<HIDN;i+=4){
                    p0 += s_vals[i  ]*W_out[(i  )*VV + j];
                    p1 += s_vals[i+1]*W_out[(i+1)*VV + j];
                    p2 += s_vals[i+2]*W_out[(i+2)*VV + j];
                    p3 += s_vals[i+3]*W_out[(i+3)*VV + j];
                }
                probs_out[(size_t)(b*TT + t)*VV + j] = b_out[j] + ((p0+p1)+(p2+p3));
            }
        }
        // no gsync: next X's A23 (blocks 0-7) runs after D2 on the same
        // blocks; other blocks' conv reads nothing D2 writes. Shared reuse
        // is sealed by the loop-top __syncthreads.
    }
}

// ---------------- launch ----------------
extern "C" void kernel_launch(void* const* d_in, const int* in_sizes, int n_in,
                              void* d_out, int out_size){
    const float* cnn     = (const float*)d_in[0];
    const int*   labels  = (const int*  )d_in[1];
    const float* locp    = (const float*)d_in[2];
    const float* imask   = (const float*)d_in[3];
    const float* W_init  = (const float*)d_in[5];
    const float* b_init  = (const float*)d_in[6];
    const float* emb     = (const float*)d_in[7];
    const float* W_ih    = (const float*)d_in[8];
    const float* W_hh    = (const float*)d_in[9];
    const float* b_ih    = (const float*)d_in[10];
    const float* b_hh    = (const float*)d_in[11];
    const float* W_q     = (const float*)d_in[12];
    const float* b_q     = (const float*)d_in[13];
    const float* K_cov   = (const float*)d_in[14];
    const float* W_cov   = (const float*)d_in[15];
    const float* w_alpha = (const float*)d_in[16];
    const float* b_alpha = (const float*)d_in[17];
    const float* K_feat  = (const float*)d_in[18];
    const float* b_feat  = (const float*)d_in[19];
    const float* W_state = (const float*)d_in[20];
    const float* b_state = (const float*)d_in[21];
    const float* W_emb   = (const float*)d_in[22];
    const float* b_emb   = (const float*)d_in[23];
    const float* W_ctx   = (const float*)d_in[24];
    const float* b_ctx   = (const float*)d_in[25];
    const float* W_out   = (const float*)d_in[26];
    const float* b_out   = (const float*)d_in[27];
    const float* W_loc   = (const float*)d_in[28];
    const float* b_loc   = (const float*)d_in[29];

    float* out        = (float*)d_out;
    float* probs_out  = out;                                   // B*T*V
    float* alphas_out = probs_out + (size_t)BB*TT*VV;          // B*T*H*W
    float* ctxs_out   = alphas_out + (size_t)BB*TT*HWN;        // T*B*C
    float* outs_out   = ctxs_out + (size_t)TT*BB*CC;           // T*B*HID

    k_prep<<<1489, 256>>>(W_ih, W_hh, K_feat, K_cov, W_cov);
    k_avgmask<<<dim3(8, BB), 256>>>(imask, cnn);
    k_trans<<<dim3(4, HH, BB), 256>>>(cnn, b_feat);

    k_persist<<<NBLK, 256>>>(labels, emb, b_ih, b_hh, W_q, b_q,
                             w_alpha, b_alpha, cnn,
                             W_state, b_state, W_emb, b_emb,
                             W_ctx, b_ctx, W_out, b_out,
                             W_init, b_init, locp, W_loc, b_loc,
                             probs_out, alphas_out, ctxs_out, outs_out);
    (void)in_sizes; (void)n_in; (void)out_size;
}